// round 8
// baseline (speedup 1.0000x reference)
#include <cuda_runtime.h>
#include <math.h>

#define E_N 100000
#define D_N 300
#define R_N 1000
#define T_N 10000
#define K_N 25
#define SD  320           // padded row stride (floats)
#define D4  75            // 300/4 float4 per real row
#define SD4 80            // 320/4 float4 per padded row
#define GAMMA_F 1.0f

// ---------------- scratch (device globals: allocation-free) ----------------
__device__ float g_emb[(size_t)E_N * SD];
__device__ float g_A1 [(size_t)E_N * SD];
__device__ float g_A2 [(size_t)E_N * SD];
__device__ float g_A3 [(size_t)E_N * SD];
__device__ float g_A5 [(size_t)E_N * SD];
__device__ float g_A6 [(size_t)E_N * SD];
__device__ float g_Lm [R_N * SD];
__device__ float g_Rm [R_N * SD];
__device__ float g_P  [R_N * SD];
__device__ float g_Wt [6 * SD * SD];   // 0:Dt 1:Db1 2:Db2 3:W1 4:W2 5:KG

// ---------------- helpers ----------------
__device__ __forceinline__ float warp_sum(float v) {
#pragma unroll
    for (int o = 16; o > 0; o >>= 1) v += __shfl_xor_sync(0xffffffffu, v, o);
    return v;
}

__device__ __forceinline__ unsigned long long bcast2(float x) {
    unsigned long long r;
    asm("mov.b64 %0, {%1, %1};" : "=l"(r) : "f"(x));
    return r;
}
__device__ __forceinline__ float2 unpack2(unsigned long long v) {
    float2 f;
    asm("mov.b64 {%0, %1}, %2;" : "=f"(f.x), "=f"(f.y) : "l"(v));
    return f;
}
__device__ __forceinline__ void ffma2(unsigned long long& d, unsigned long long a, unsigned long long b) {
    asm("fma.rn.f32x2 %0, %1, %2, %0;" : "+l"(d) : "l"(a), "l"(b));
}
__device__ __forceinline__ void red_add_v4(float* p, float a, float b, float c, float d) {
    asm volatile("red.global.add.v4.f32 [%0], {%1, %2, %3, %4};"
                 :: "l"(p), "f"(a), "f"(b), "f"(c), "f"(d) : "memory");
}

// ---------------- small kernels ----------------
__global__ void zero_out_kernel(float* out) { if (threadIdx.x == 0 && blockIdx.x == 0) out[0] = 0.0f; }

__global__ void zero4_kernel(float4* p, int n4) {
    int i = blockIdx.x * blockDim.x + threadIdx.x;
    if (i < n4) p[i] = make_float4(0.f, 0.f, 0.f, 0.f);
}

__global__ void pad_weights_kernel(const float* __restrict__ Dense,
                                   const float* __restrict__ W1,
                                   const float* __restrict__ W2,
                                   const float* __restrict__ KG) {
    int idx = blockIdx.x * blockDim.x + threadIdx.x;
    const int total = 6 * SD * SD;
    if (idx >= total) return;
    int w   = idx / (SD * SD);
    int rem = idx % (SD * SD);
    int r = rem / SD, c = rem % SD;
    float v = 0.f;
    if (r < D_N && c < D_N) {
        if      (w == 0) v = Dense[(size_t)r * D_N + c];
        else if (w == 1) v = Dense[(size_t)(D_N + r) * D_N + c];
        else if (w == 2) v = Dense[(size_t)(2 * D_N + r) * D_N + c];
        else if (w == 3) v = W1[(size_t)r * D_N + c];
        else if (w == 4) v = W2[(size_t)r * D_N + c];
        else             v = KG[(size_t)r * D_N + c];
    }
    g_Wt[idx] = v;
}

__global__ void normalize_kernel(const float* __restrict__ we) {
    int warp = (blockIdx.x * blockDim.x + threadIdx.x) >> 5;
    int lane = threadIdx.x & 31;
    if (warp >= E_N) return;
    const float4* src = (const float4*)(we + (size_t)warp * D_N);
    float4 v[3];
    float s = 0.f;
#pragma unroll
    for (int it = 0; it < 3; it++) {
        int j = lane + it * 32;
        if (j < D4) {
            float4 x = src[j];
            v[it] = x;
            s += x.x * x.x + x.y * x.y + x.z * x.z + x.w * x.w;
        } else {
            v[it] = make_float4(0.f, 0.f, 0.f, 0.f);
        }
    }
    s = warp_sum(s);
    float inv = 1.0f / sqrtf(s);
    float4* dst = (float4*)(g_emb + (size_t)warp * SD);
#pragma unroll
    for (int it = 0; it < 3; it++) {
        int j = lane + it * 32;
        if (j < D4)       dst[j] = make_float4(v[it].x * inv, v[it].y * inv, v[it].z * inv, v[it].w * inv);
        else if (j < SD4) dst[j] = make_float4(0.f, 0.f, 0.f, 0.f);
    }
}

// COO SpMM scatter with vector reductions. Warp per nnz.
__global__ void spmm_kernel(const int* __restrict__ rows, const int* __restrict__ cols,
                            const float* __restrict__ vals, int nnz,
                            const float* __restrict__ X, float* __restrict__ Out,
                            int rel_mode) {
    int warp = (blockIdx.x * blockDim.x + threadIdx.x) >> 5;
    int lane = threadIdx.x & 31;
    if (warp >= nnz) return;
    int   r = rows[warp];
    int   c = cols[warp];
    float v = vals[warp];
    if (rel_mode && c >= R_N) { c -= R_N; v = -v; }
    const float4* xr = (const float4*)(X + (size_t)c * SD);
    float* orow = Out + (size_t)r * SD;
#pragma unroll
    for (int it = 0; it < 3; it++) {
        int j = lane + it * 32;
        if (j < D4) {
            float4 x = xr[j];
            red_add_v4(orow + j * 4, v * x.x, v * x.y, v * x.z, v * x.w);
        }
    }
}

// ---------------- SGEMM (packed f32x2, double-buffered): C = A[M,304] @ B[304,320] ----------------
// mode 0: store; mode 1: C += ; mode 3: highway epilogue
//   tg = sigmoid(acc + epv[d]); C = tg*relu(ep2) + (1-tg)*ep1 ; pads -> 0
#define BM 256
#define BN 64
#define BK 16
#define KTILES 19   // K = 304 >= 300, pad cols 300..303 are guaranteed zero
__global__ __launch_bounds__(256, 2) void sgemm_kernel(const float* __restrict__ A,
                                                       const float* __restrict__ B,
                                                       float* __restrict__ C,
                                                       int M, int mode,
                                                       const float* __restrict__ ep1,
                                                       const float* __restrict__ ep2,
                                                       const float* __restrict__ epv) {
    __shared__ float As[2][BK][BM];
    __shared__ float Bs[2][BK][BN];
    int bm = blockIdx.y * BM;
    int bn = blockIdx.x * BN;
    int tid = threadIdx.x;
    int tx = tid & 7;      // 8 col-groups of 8
    int ty = tid >> 3;     // 32 row-groups of 8
    int arow = bm + tid;
    bool avalid = arow < M;
    const float* Aptr = A + (size_t)arow * SD;
    int brow  = tid >> 4;  // 0..15
    int bcol4 = tid & 15;
    const float* Bptr = B + (size_t)brow * SD + bn + bcol4 * 4;

    unsigned long long acc[8][4];
#pragma unroll
    for (int i = 0; i < 8; i++)
#pragma unroll
        for (int j = 0; j < 4; j++) acc[i][j] = 0ull;

    float4 ra[4], rb;
    // prologue: tile 0 -> stage 0
#pragma unroll
    for (int c = 0; c < 4; c++)
        ra[c] = avalid ? *(const float4*)(Aptr + c * 4) : make_float4(0.f, 0.f, 0.f, 0.f);
    rb = *(const float4*)(Bptr);
#pragma unroll
    for (int c = 0; c < 4; c++) {
        As[0][c * 4 + 0][tid] = ra[c].x;
        As[0][c * 4 + 1][tid] = ra[c].y;
        As[0][c * 4 + 2][tid] = ra[c].z;
        As[0][c * 4 + 3][tid] = ra[c].w;
    }
    *(float4*)(&Bs[0][brow][bcol4 * 4]) = rb;
    __syncthreads();

    for (int t = 0; t < KTILES; t++) {
        int cur = t & 1, nxt = cur ^ 1;
        if (t + 1 < KTILES) {
            int k0 = (t + 1) * BK;
#pragma unroll
            for (int c = 0; c < 4; c++)
                ra[c] = avalid ? *(const float4*)(Aptr + k0 + c * 4) : make_float4(0.f, 0.f, 0.f, 0.f);
            rb = *(const float4*)(Bptr + (size_t)k0 * SD);
        }
#pragma unroll
        for (int k = 0; k < BK; k++) {
            ulonglong2 bb0 = *(const ulonglong2*)(&Bs[cur][k][tx * 8]);
            ulonglong2 bb1 = *(const ulonglong2*)(&Bs[cur][k][tx * 8 + 4]);
            unsigned long long b2[4] = {bb0.x, bb0.y, bb1.x, bb1.y};
            float4 a0 = *(const float4*)(&As[cur][k][ty * 8]);
            float4 a1 = *(const float4*)(&As[cur][k][ty * 8 + 4]);
            unsigned long long a2[8];
            a2[0] = bcast2(a0.x); a2[1] = bcast2(a0.y); a2[2] = bcast2(a0.z); a2[3] = bcast2(a0.w);
            a2[4] = bcast2(a1.x); a2[5] = bcast2(a1.y); a2[6] = bcast2(a1.z); a2[7] = bcast2(a1.w);
#pragma unroll
            for (int i = 0; i < 8; i++)
#pragma unroll
                for (int j = 0; j < 4; j++)
                    ffma2(acc[i][j], a2[i], b2[j]);
        }
        if (t + 1 < KTILES) {
#pragma unroll
            for (int c = 0; c < 4; c++) {
                As[nxt][c * 4 + 0][tid] = ra[c].x;
                As[nxt][c * 4 + 1][tid] = ra[c].y;
                As[nxt][c * 4 + 2][tid] = ra[c].z;
                As[nxt][c * 4 + 3][tid] = ra[c].w;
            }
            *(float4*)(&Bs[nxt][brow][bcol4 * 4]) = rb;
        }
        __syncthreads();
    }

    int gcol = bn + tx * 8;
#pragma unroll
    for (int i = 0; i < 8; i++) {
        int grow = bm + ty * 8 + i;
        if (grow >= M) continue;
        float2 u0 = unpack2(acc[i][0]);
        float2 u1 = unpack2(acc[i][1]);
        float2 u2 = unpack2(acc[i][2]);
        float2 u3 = unpack2(acc[i][3]);
        float vals[8] = {u0.x, u0.y, u1.x, u1.y, u2.x, u2.y, u3.x, u3.y};
        float* crow = C + (size_t)grow * SD + gcol;
        if (mode == 0) {
            *(float4*)crow       = make_float4(vals[0], vals[1], vals[2], vals[3]);
            *(float4*)(crow + 4) = make_float4(vals[4], vals[5], vals[6], vals[7]);
        } else if (mode == 1) {
            float4 c0 = *(float4*)crow;
            float4 c1 = *(float4*)(crow + 4);
            *(float4*)crow       = make_float4(c0.x + vals[0], c0.y + vals[1], c0.z + vals[2], c0.w + vals[3]);
            *(float4*)(crow + 4) = make_float4(c1.x + vals[4], c1.y + vals[5], c1.z + vals[6], c1.w + vals[7]);
        } else {
            const float* l1 = ep1 + (size_t)grow * SD + gcol;
            const float* gc = ep2 + (size_t)grow * SD + gcol;
#pragma unroll
            for (int j = 0; j < 8; j++) {
                int d = gcol + j;
                float o = 0.f;
                if (d < D_N) {
                    float tg = 1.0f / (1.0f + expf(-(vals[j] + epv[d])));
                    float g  = fmaxf(gc[j], 0.f);
                    o = tg * g + (1.0f - tg) * l1[j];
                }
                crow[j] = o;
            }
        }
    }
}

// h = emb + relu(h_pre + Bias); pads -> 0. float4-vectorized.
__global__ void h_kernel(const float* __restrict__ Bias) {
    int i = blockIdx.x * blockDim.x + threadIdx.x;     // float4 index
    if (i >= E_N * SD4) return;
    int j = i % SD4;
    float4 o = make_float4(0.f, 0.f, 0.f, 0.f);
    if (j < D4) {
        float4 p = ((const float4*)g_A1)[i];
        float4 e = ((const float4*)g_emb)[i];
        int d = j * 4;
        o.x = e.x + fmaxf(p.x + Bias[d + 0], 0.f);
        o.y = e.y + fmaxf(p.y + Bias[d + 1], 0.f);
        o.z = e.z + fmaxf(p.z + Bias[d + 2], 0.f);
        o.w = e.w + fmaxf(p.w + Bias[d + 3], 0.f);
    }
    ((float4*)g_A2)[i] = o;
}

// Fused hinge loss: one block per pair t.
__global__ __launch_bounds__(256) void loss_kernel(const int* __restrict__ pl,
                                                   const int* __restrict__ pr,
                                                   const int* __restrict__ nr,
                                                   const int* __restrict__ nl,
                                                   const float* __restrict__ mask,
                                                   const float* __restrict__ node,
                                                   float* __restrict__ out) {
    __shared__ float4 sl[D4], sr[D4];
    __shared__ float wpart[8];
    __shared__ float s_dm;
    int t    = blockIdx.x;
    int tid  = threadIdx.x;
    int lane = tid & 31;
    int wid  = tid >> 5;

    const float4* xl = (const float4*)(node + (size_t)pl[t] * SD);
    const float4* xr = (const float4*)(node + (size_t)pr[t] * SD);
    float d = 0.f;
    if (tid < D4) {
        float4 a = xl[tid], b = xr[tid];
        sl[tid] = a; sr[tid] = b;
        d = fabsf(a.x - b.x) + fabsf(a.y - b.y) + fabsf(a.z - b.z) + fabsf(a.w - b.w);
    }
    d = warp_sum(d);
    if (lane == 0) wpart[wid] = d;
    __syncthreads();
    if (tid == 0) s_dm = wpart[0] + wpart[1] + wpart[2] + GAMMA_F;
    __syncthreads();
    float dm = s_dm;

    float hsum = 0.f;
    for (int k = wid; k < K_N; k += 8) {
        int i = t * K_N + k;
        const float4* xR = (const float4*)(node + (size_t)nr[i] * SD);
        const float4* xL = (const float4*)(node + (size_t)nl[i] * SD);
        float s1 = 0.f, s2 = 0.f;
#pragma unroll
        for (int it = 0; it < 3; it++) {
            int j = lane + it * 32;
            if (j < D4) {
                float4 a = sl[j], b = sr[j], cr = xR[j], cl = xL[j];
                s1 += fabsf(a.x - cr.x) + fabsf(a.y - cr.y) + fabsf(a.z - cr.z) + fabsf(a.w - cr.w);
                s2 += fabsf(cl.x - b.x) + fabsf(cl.y - b.y) + fabsf(cl.z - b.z) + fabsf(cl.w - b.w);
            }
        }
        s1 = warp_sum(s1);
        s2 = warp_sum(s2);
        if (lane == 0) hsum += (fmaxf(dm - s1, 0.f) + fmaxf(dm - s2, 0.f)) * mask[i];
    }
    if (lane == 0) wpart[wid] = hsum;
    __syncthreads();
    if (tid == 0) {
        float tot = 0.f;
#pragma unroll
        for (int w = 0; w < 8; w++) tot += wpart[w];
        atomicAdd(out, tot * 0.5f);
    }
}

// ---------------- host ----------------
extern "C" void kernel_launch(void* const* d_in, const int* in_sizes, int n_in,
                              void* d_out, int out_size) {
    const float* we    = (const float*)d_in[0];
    const float* kgw   = (const float*)d_in[1];
    const float* bg    = (const float*)d_in[2];
    const float* W1    = (const float*)d_in[3];
    const float* W2    = (const float*)d_in[4];
    const float* Dense = (const float*)d_in[5];
    const float* Bias  = (const float*)d_in[6];
    const int*   hr_rows = (const int*)d_in[7];
    const int*   hr_cols = (const int*)d_in[8];
    const float* hr_vals = (const float*)d_in[9];
    const int*   tr_rows = (const int*)d_in[10];
    const int*   tr_cols = (const int*)d_in[11];
    const float* tr_vals = (const float*)d_in[12];
    const int*   er_rows = (const int*)d_in[13];
    const int*   er_cols = (const int*)d_in[14];
    const float* er_vals = (const float*)d_in[15];
    const int*   adj_rows = (const int*)d_in[16];
    const int*   adj_cols = (const int*)d_in[17];
    const float* adj_vals = (const float*)d_in[18];
    const int*   pos_left  = (const int*)d_in[19];
    const int*   pos_right = (const int*)d_in[20];
    const int*   neg_right = (const int*)d_in[21];
    const int*   neg_left  = (const int*)d_in[22];
    const float* mask      = (const float*)d_in[23];
    float* out = (float*)d_out;

    int nnz_hr  = in_sizes[7];
    int nnz_tr  = in_sizes[10];
    int nnz_er  = in_sizes[13];
    int nnz_adj = in_sizes[16];

    float *p_emb, *p_A1, *p_A2, *p_A3, *p_A5, *p_A6, *p_Lm, *p_Rm, *p_P, *p_Wt;
    cudaGetSymbolAddress((void**)&p_emb, g_emb);
    cudaGetSymbolAddress((void**)&p_A1,  g_A1);
    cudaGetSymbolAddress((void**)&p_A2,  g_A2);
    cudaGetSymbolAddress((void**)&p_A3,  g_A3);
    cudaGetSymbolAddress((void**)&p_A5,  g_A5);
    cudaGetSymbolAddress((void**)&p_A6,  g_A6);
    cudaGetSymbolAddress((void**)&p_Lm,  g_Lm);
    cudaGetSymbolAddress((void**)&p_Rm,  g_Rm);
    cudaGetSymbolAddress((void**)&p_P,   g_P);
    cudaGetSymbolAddress((void**)&p_Wt,  g_Wt);

    const int ELEM = E_N * SD;
    dim3 gemmGridE(SD / BN, (E_N + BM - 1) / BM);   // (5, 391): cols fast -> A reuse in L2
    dim3 gemmGridR(SD / BN, (R_N + BM - 1) / BM);   // (5, 4)

    // launches 1-5 (launch #6 = big GEMM, so ncu -s 5 -c 1 profiles it)
    zero_out_kernel<<<1, 1>>>(out);
    pad_weights_kernel<<<(6 * SD * SD + 255) / 256, 256>>>(Dense, W1, W2, kgw);
    normalize_kernel<<<(E_N * 32) / 256, 256>>>(we);
    zero4_kernel<<<(R_N * SD / 4 + 255) / 256, 256>>>((float4*)p_Lm, R_N * SD / 4);
    zero4_kernel<<<(R_N * SD / 4 + 255) / 256, 256>>>((float4*)p_Rm, R_N * SD / 4);

    // 6: h_pre partial = emb @ Dense_top -> A1   (PROFILED LAUNCH)
    sgemm_kernel<<<gemmGridE, 256>>>(p_emb, p_Wt + 0 * SD * SD, p_A1, E_N, 0, 0, 0, 0);

    // relation aggregation: L, Rm
    spmm_kernel<<<(nnz_hr + 7) / 8, 256>>>(hr_rows, hr_cols, hr_vals, nnz_hr, p_emb, p_Lm, 0);
    spmm_kernel<<<(nnz_tr + 7) / 8, 256>>>(tr_rows, tr_cols, tr_vals, nnz_tr, p_emb, p_Rm, 0);

    // P = L @ Db1 + Rm @ Db2  (Dense_bot pushed through the er-spmm)
    sgemm_kernel<<<gemmGridR, 256>>>(p_Lm, p_Wt + 1 * SD * SD, p_P, R_N, 0, 0, 0, 0);
    sgemm_kernel<<<gemmGridR, 256>>>(p_Rm, p_Wt + 2 * SD * SD, p_P, R_N, 1, 0, 0, 0);

    // h_pre += spmm(er, +-P)
    spmm_kernel<<<(nnz_er + 7) / 8, 256>>>(er_rows, er_cols, er_vals, nnz_er, p_P, p_A1, 1);

    // h = emb + relu(h_pre + Bias)
    h_kernel<<<(E_N * SD4 + 255) / 256, 256>>>(Bias);

    // layer 1: t1 = h@W1 -> A3; gcn1 accum in A5; gate GEMM fuses highway -> A6
    sgemm_kernel<<<gemmGridE, 256>>>(p_A2, p_Wt + 3 * SD * SD, p_A3, E_N, 0, 0, 0, 0);
    zero4_kernel<<<(ELEM / 4 + 255) / 256, 256>>>((float4*)p_A5, ELEM / 4);
    spmm_kernel<<<(nnz_adj + 7) / 8, 256>>>(adj_rows, adj_cols, adj_vals, nnz_adj, p_A3, p_A5, 0);
    sgemm_kernel<<<gemmGridE, 256>>>(p_A2, p_Wt + 5 * SD * SD, p_A6, E_N, 3, p_A2, p_A5, bg);

    // layer 2: t2 = hg1@W2 -> A3; gcn2 accum in A1; gate GEMM fuses highway -> node (A2)
    sgemm_kernel<<<gemmGridE, 256>>>(p_A6, p_Wt + 4 * SD * SD, p_A3, E_N, 0, 0, 0, 0);
    zero4_kernel<<<(ELEM / 4 + 255) / 256, 256>>>((float4*)p_A1, ELEM / 4);
    spmm_kernel<<<(nnz_adj + 7) / 8, 256>>>(adj_rows, adj_cols, adj_vals, nnz_adj, p_A3, p_A1, 0);
    sgemm_kernel<<<gemmGridE, 256>>>(p_A6, p_Wt + 5 * SD * SD, p_A2, E_N, 3, p_A6, p_A1, bg);

    // fused loss
    loss_kernel<<<T_N, 256>>>(pos_left, pos_right, neg_right, neg_left, mask, p_A2, out);
    (void)n_in; (void)out_size;
}

// round 10
// speedup vs baseline: 1.6540x; 1.6540x over previous
#include <cuda_runtime.h>
#include <cuda_bf16.h>
#include <math.h>
#include <stdint.h>

#define E_N 100000
#define D_N 300
#define R_N 1000
#define T_N 10000
#define K_N 25
#define SD  320           // padded row stride (floats)
#define D4  75
#define SD4 80
#define GAMMA_F 1.0f
#define WOFF (320*320)

// ---------------- scratch (device globals: allocation-free) ----------------
__device__ float g_emb[(size_t)E_N * SD];
__device__ float g_A1 [(size_t)E_N * SD];
__device__ float g_A2 [(size_t)E_N * SD];
__device__ float g_A3 [(size_t)E_N * SD];
__device__ float g_A5 [(size_t)E_N * SD];
__device__ float g_A6 [(size_t)E_N * SD];
__device__ float g_Lm [R_N * SD];
__device__ float g_Rm [R_N * SD];
__device__ float g_P  [R_N * SD];
__device__ float g_Wt [2 * SD * SD];              // fp32 padded Db1, Db2 (small GEMMs)
__device__ __nv_bfloat16 g_Bh[(size_t)E_N * SD];  // activation hi split
__device__ __nv_bfloat16 g_Bl[(size_t)E_N * SD];  // activation lo split
__device__ __nv_bfloat16 g_WTh[4 * WOFF];         // transposed weights hi: 0:Dt 1:W1 2:W2 3:KG
__device__ __nv_bfloat16 g_WTl[4 * WOFF];         // transposed weights lo

// ---------------- helpers ----------------
__device__ __forceinline__ uint32_t smem_to_u32(const void* p) {
    uint32_t a;
    asm("{ .reg .u64 t; cvta.to.shared.u64 t, %1; cvt.u32.u64 %0, t; }" : "=r"(a) : "l"(p));
    return a;
}
__device__ __forceinline__ float warp_sum(float v) {
#pragma unroll
    for (int o = 16; o > 0; o >>= 1) v += __shfl_xor_sync(0xffffffffu, v, o);
    return v;
}
__device__ __forceinline__ unsigned long long bcast2(float x) {
    unsigned long long r;
    asm("mov.b64 %0, {%1, %1};" : "=l"(r) : "f"(x));
    return r;
}
__device__ __forceinline__ float2 unpack2(unsigned long long v) {
    float2 f;
    asm("mov.b64 {%0, %1}, %2;" : "=f"(f.x), "=f"(f.y) : "l"(v));
    return f;
}
__device__ __forceinline__ void ffma2(unsigned long long& d, unsigned long long a, unsigned long long b) {
    asm("fma.rn.f32x2 %0, %1, %2, %0;" : "+l"(d) : "l"(a), "l"(b));
}
__device__ __forceinline__ void red_add_v4(float* p, float a, float b, float c, float d) {
    asm volatile("red.global.add.v4.f32 [%0], {%1, %2, %3, %4};"
                 :: "l"(p), "f"(a), "f"(b), "f"(c), "f"(d) : "memory");
}
// cp.async (sm_80 baseline PTX — safe for compute_103 base target)
__device__ __forceinline__ void cp16(uint32_t dst, const void* src, int src_bytes) {
    asm volatile("cp.async.cg.shared.global [%0], [%1], 16, %2;"
                 :: "r"(dst), "l"(src), "r"(src_bytes) : "memory");
}
#define CP_COMMIT() asm volatile("cp.async.commit_group;" ::: "memory")
template <int N>
__device__ __forceinline__ void cp_wait() {
    asm volatile("cp.async.wait_group %0;" :: "n"(N) : "memory");
}
__device__ __forceinline__ void ldsm4(uint32_t* r, uint32_t addr) {
    asm volatile("ldmatrix.sync.aligned.m8n8.x4.shared.b16 {%0,%1,%2,%3}, [%4];"
                 : "=r"(r[0]), "=r"(r[1]), "=r"(r[2]), "=r"(r[3]) : "r"(addr));
}
__device__ __forceinline__ void mma16816(float* d, const uint32_t* a, uint32_t b0, uint32_t b1) {
    asm volatile("mma.sync.aligned.m16n8k16.row.col.f32.bf16.bf16.f32 "
                 "{%0,%1,%2,%3}, {%4,%5,%6,%7}, {%8,%9}, {%0,%1,%2,%3};"
                 : "+f"(d[0]), "+f"(d[1]), "+f"(d[2]), "+f"(d[3])
                 : "r"(a[0]), "r"(a[1]), "r"(a[2]), "r"(a[3]), "r"(b0), "r"(b1));
}

// ---------------- small kernels ----------------
__global__ void zero_out_kernel(float* out) { if (threadIdx.x == 0 && blockIdx.x == 0) out[0] = 0.0f; }

__global__ void zero4_kernel(float4* p, int n4) {
    int i = blockIdx.x * blockDim.x + threadIdx.x;
    if (i < n4) p[i] = make_float4(0.f, 0.f, 0.f, 0.f);
}

// fp32 padded weights for the small R-GEMMs: 0:Db1 (Dense rows 300-599), 1:Db2 (600-899)
__global__ void pad_weights_kernel(const float* __restrict__ Dense) {
    int idx = blockIdx.x * blockDim.x + threadIdx.x;
    if (idx >= 2 * SD * SD) return;
    int w = idx / (SD * SD);
    int rem = idx % (SD * SD);
    int r = rem / SD, c = rem % SD;
    float v = 0.f;
    if (r < D_N && c < D_N) v = Dense[(size_t)(D_N * (1 + w) + r) * D_N + c];
    g_Wt[idx] = v;
}

// transposed bf16 hi/lo weight splits: [w][n][k] = M_w[k, n]
__global__ void wsplit_kernel(const float* __restrict__ Dense, const float* __restrict__ W1,
                              const float* __restrict__ W2, const float* __restrict__ KG) {
    int idx = blockIdx.x * blockDim.x + threadIdx.x;
    if (idx >= 4 * WOFF) return;
    int w = idx / WOFF;
    int rem = idx % WOFF;
    int n = rem / 320, k = rem % 320;
    float v = 0.f;
    if (n < D_N && k < D_N) {
        const float* src = (w == 0) ? Dense : (w == 1) ? W1 : (w == 2) ? W2 : KG;
        v = src[(size_t)k * D_N + n];
    }
    __nv_bfloat16 hi = __float2bfloat16_rn(v);
    __nv_bfloat16 lo = __float2bfloat16_rn(v - __bfloat162float(hi));
    g_WTh[idx] = hi;
    g_WTl[idx] = lo;
}

// fp32 [E,320] -> bf16 hi/lo splits
__global__ void csplit_kernel(const float* __restrict__ X) {
    int i = blockIdx.x * blockDim.x + threadIdx.x;   // float4 index
    if (i >= E_N * SD4) return;
    float4 v = ((const float4*)X)[i];
    float xs[4] = {v.x, v.y, v.z, v.w};
    __nv_bfloat162 h0, h1, l0, l1;
    __nv_bfloat16 h[4], l[4];
#pragma unroll
    for (int q = 0; q < 4; q++) {
        h[q] = __float2bfloat16_rn(xs[q]);
        l[q] = __float2bfloat16_rn(xs[q] - __bfloat162float(h[q]));
    }
    h0.x = h[0]; h0.y = h[1]; h1.x = h[2]; h1.y = h[3];
    l0.x = l[0]; l0.y = l[1]; l1.x = l[2]; l1.y = l[3];
    ((__nv_bfloat162*)g_Bh)[2 * i]     = h0;
    ((__nv_bfloat162*)g_Bh)[2 * i + 1] = h1;
    ((__nv_bfloat162*)g_Bl)[2 * i]     = l0;
    ((__nv_bfloat162*)g_Bl)[2 * i + 1] = l1;
}

__global__ void normalize_kernel(const float* __restrict__ we) {
    int warp = (blockIdx.x * blockDim.x + threadIdx.x) >> 5;
    int lane = threadIdx.x & 31;
    if (warp >= E_N) return;
    const float4* src = (const float4*)(we + (size_t)warp * D_N);
    float4 v[3];
    float s = 0.f;
#pragma unroll
    for (int it = 0; it < 3; it++) {
        int j = lane + it * 32;
        if (j < D4) {
            float4 x = src[j];
            v[it] = x;
            s += x.x * x.x + x.y * x.y + x.z * x.z + x.w * x.w;
        } else v[it] = make_float4(0.f, 0.f, 0.f, 0.f);
    }
    s = warp_sum(s);
    float inv = 1.0f / sqrtf(s);
    float4* dst = (float4*)(g_emb + (size_t)warp * SD);
#pragma unroll
    for (int it = 0; it < 3; it++) {
        int j = lane + it * 32;
        if (j < D4)       dst[j] = make_float4(v[it].x * inv, v[it].y * inv, v[it].z * inv, v[it].w * inv);
        else if (j < SD4) dst[j] = make_float4(0.f, 0.f, 0.f, 0.f);
    }
}

// COO SpMM scatter with vector reductions. Warp per nnz.
__global__ void spmm_kernel(const int* __restrict__ rows, const int* __restrict__ cols,
                            const float* __restrict__ vals, int nnz,
                            const float* __restrict__ X, float* __restrict__ Out,
                            int rel_mode) {
    int warp = (blockIdx.x * blockDim.x + threadIdx.x) >> 5;
    int lane = threadIdx.x & 31;
    if (warp >= nnz) return;
    int   r = rows[warp];
    int   c = cols[warp];
    float v = vals[warp];
    if (rel_mode && c >= R_N) { c -= R_N; v = -v; }
    const float4* xr = (const float4*)(X + (size_t)c * SD);
    float* orow = Out + (size_t)r * SD;
#pragma unroll
    for (int it = 0; it < 3; it++) {
        int j = lane + it * 32;
        if (j < D4) {
            float4 x = xr[j];
            red_add_v4(orow + j * 4, v * x.x, v * x.y, v * x.z, v * x.w);
        }
    }
}

// ---------------- HMMA GEMM (bf16 split-2, mma.sync): C[M,320] = X @ W ----------------
// Xh/Xl: [M,320] bf16 K-major. Wh/Wl: [320(n),320(k)] bf16 (W transposed).
// Block 128(m) x 64(n), 8 warps (2m x 4n), warp tile 64x16. K-chunk 64, double buffered.
// mode 0: store; mode 3: highway epilogue.
#define MMS 72                         // smem row stride in bf16 (64 + 8 pad)
#define A_TB (128 * MMS * 2)           // 18432 bytes per A tile
#define B_TB (64 * MMS * 2)            // 9216
#define MM_STAGE (2 * A_TB + 2 * B_TB) // 55296
#define MM_SMEM  (2 * MM_STAGE)        // 110592

__device__ __forceinline__ void mm_load_stage(uint32_t sb,
                                              const __nv_bfloat16* Xh, const __nv_bfloat16* Xl,
                                              const __nv_bfloat16* Wh, const __nv_bfloat16* Wl,
                                              int bm, int bn, int M, int k0, int tid) {
#pragma unroll
    for (int q = 0; q < 12; q++) {
        int idx = q * 256 + tid;
        if (idx < 2048) {
            int part = idx >> 10;              // 0: Ah, 1: Al
            int r = (idx & 1023) >> 3, c = idx & 7;
            const __nv_bfloat16* src = (part ? Xl : Xh) + (size_t)(bm + r) * 320 + k0 + c * 8;
            int ok = (bm + r < M) ? 16 : 0;
            cp16(sb + part * A_TB + r * (MMS * 2) + c * 16, src, ok);
        } else {
            int part = (idx - 2048) >> 9;      // 0: Bh, 1: Bl
            int rr = (idx - 2048) & 511;
            int r = rr >> 3, c = rr & 7;
            const __nv_bfloat16* src = (part ? Wl : Wh) + (size_t)(bn + r) * 320 + k0 + c * 8;
            cp16(sb + 2 * A_TB + part * B_TB + r * (MMS * 2) + c * 16, src, 16);
        }
    }
    CP_COMMIT();
}

__global__ __launch_bounds__(256) void mgemm_kernel(const __nv_bfloat16* __restrict__ Xh,
                                                    const __nv_bfloat16* __restrict__ Xl,
                                                    const __nv_bfloat16* __restrict__ Wh,
                                                    const __nv_bfloat16* __restrict__ Wl,
                                                    float* __restrict__ C, int M, int mode,
                                                    const float* __restrict__ ep1,
                                                    const float* __restrict__ ep2,
                                                    const float* __restrict__ epv) {
    extern __shared__ char sm8[];
    uint32_t smb = smem_to_u32(sm8);
    int tid = threadIdx.x, wid = tid >> 5, lane = tid & 31;
    int bn = blockIdx.x * 64, bm = blockIdx.y * 128;
    int wm = (wid >> 2) * 64;      // 2 warp groups along m
    int wn = (wid & 3) * 16;       // 4 along n

    float acc[4][2][4];
#pragma unroll
    for (int i = 0; i < 4; i++)
#pragma unroll
        for (int j = 0; j < 2; j++)
#pragma unroll
            for (int q = 0; q < 4; q++) acc[i][j][q] = 0.f;

    // ldmatrix lane address components (element offsets within tile)
    int aRow = lane & 15, aKsel = (lane >> 4) * 8;                 // A: x4 -> (m0-7,k0),(m8-15,k0),(m0-7,k8),(m8-15,k8)
    int bRow = (lane >> 4) * 8 + (lane & 7), bKsel = ((lane >> 3) & 1) * 8;  // B: n-tile pairs

    mm_load_stage(smb, Xh, Xl, Wh, Wl, bm, bn, M, 0, tid);

    for (int ch = 0; ch < 5; ch++) {
        uint32_t sb = smb + (ch & 1) * MM_STAGE;
        if (ch + 1 < 5)
            mm_load_stage(smb + ((ch + 1) & 1) * MM_STAGE, Xh, Xl, Wh, Wl, bm, bn, M, (ch + 1) * 64, tid);
        if (ch + 1 < 5) cp_wait<1>(); else cp_wait<0>();
        __syncthreads();
#pragma unroll
        for (int ks = 0; ks < 4; ks++) {
            int k0 = ks * 16;
            uint32_t ah[4][4], al[4][4], bh[4], bl[4];
#pragma unroll
            for (int i = 0; i < 4; i++) {
                uint32_t ad = sb + ((wm + i * 16 + aRow) * MMS + k0 + aKsel) * 2;
                ldsm4(ah[i], ad);
                ldsm4(al[i], ad + A_TB);
            }
            uint32_t bd = sb + 2 * A_TB + ((wn + bRow) * MMS + k0 + bKsel) * 2;
            ldsm4(bh, bd);
            ldsm4(bl, bd + B_TB);
#pragma unroll
            for (int i = 0; i < 4; i++)
#pragma unroll
                for (int j = 0; j < 2; j++) {
                    mma16816(acc[i][j], ah[i], bh[j * 2], bh[j * 2 + 1]);
                    mma16816(acc[i][j], ah[i], bl[j * 2], bl[j * 2 + 1]);
                    mma16816(acc[i][j], al[i], bh[j * 2], bh[j * 2 + 1]);
                }
        }
        __syncthreads();
    }

    // epilogue
#pragma unroll
    for (int i = 0; i < 4; i++)
#pragma unroll
        for (int j = 0; j < 2; j++) {
            int col = bn + wn + j * 8 + (lane & 3) * 2;
#pragma unroll
            for (int half = 0; half < 2; half++) {
                int row = bm + wm + i * 16 + (lane >> 2) + half * 8;
                if (row >= M) continue;
                float v0 = acc[i][j][half * 2], v1 = acc[i][j][half * 2 + 1];
                float* crow = C + (size_t)row * SD + col;
                if (mode == 0) {
                    *(float2*)crow = make_float2(v0, v1);
                } else {
                    const float* l1 = ep1 + (size_t)row * SD + col;
                    const float* gc = ep2 + (size_t)row * SD + col;
                    float2 a = *(const float2*)l1;
                    float2 g = *(const float2*)gc;
                    float o0 = 0.f, o1 = 0.f;
                    if (col < D_N) {
                        float tg = 1.0f / (1.0f + expf(-(v0 + epv[col])));
                        o0 = tg * fmaxf(g.x, 0.f) + (1.0f - tg) * a.x;
                    }
                    if (col + 1 < D_N) {
                        float tg = 1.0f / (1.0f + expf(-(v1 + epv[col + 1])));
                        o1 = tg * fmaxf(g.y, 0.f) + (1.0f - tg) * a.y;
                    }
                    *(float2*)crow = make_float2(o0, o1);
                }
            }
        }
}

// ---------------- FFMA2 SGEMM (small R_N GEMMs): C = A[M,304] @ B[304,320] ----------------
#define BM 256
#define BN 64
#define BK 16
#define KTILES 19
__global__ __launch_bounds__(256, 2) void sgemm_kernel(const float* __restrict__ A,
                                                       const float* __restrict__ B,
                                                       float* __restrict__ C,
                                                       int M, int accumulate) {
    __shared__ float As[2][BK][BM];
    __shared__ float Bs[2][BK][BN];
    int bm = blockIdx.y * BM;
    int bn = blockIdx.x * BN;
    int tid = threadIdx.x;
    int tx = tid & 7;
    int ty = tid >> 3;
    int arow = bm + tid;
    bool avalid = arow < M;
    const float* Aptr = A + (size_t)arow * SD;
    int brow  = tid >> 4;
    int bcol4 = tid & 15;
    const float* Bptr = B + (size_t)brow * SD + bn + bcol4 * 4;

    unsigned long long acc[8][4];
#pragma unroll
    for (int i = 0; i < 8; i++)
#pragma unroll
        for (int j = 0; j < 4; j++) acc[i][j] = 0ull;

    float4 ra[4], rb;
#pragma unroll
    for (int c = 0; c < 4; c++)
        ra[c] = avalid ? *(const float4*)(Aptr + c * 4) : make_float4(0.f, 0.f, 0.f, 0.f);
    rb = *(const float4*)(Bptr);
#pragma unroll
    for (int c = 0; c < 4; c++) {
        As[0][c * 4 + 0][tid] = ra[c].x;
        As[0][c * 4 + 1][tid] = ra[c].y;
        As[0][c * 4 + 2][tid] = ra[c].z;
        As[0][c * 4 + 3][tid] = ra[c].w;
    }
    *(float4*)(&Bs[0][brow][bcol4 * 4]) = rb;
    __syncthreads();

    for (int t = 0; t < KTILES; t++) {
        int cur = t & 1, nxt = cur ^ 1;
        if (t + 1 < KTILES) {
            int k0 = (t + 1) * BK;
#pragma unroll
            for (int c = 0; c < 4; c++)
                ra[c] = avalid ? *(const float4*)(Aptr + k0 + c * 4) : make_float4(0.f, 0.f, 0.f, 0.f);
            rb = *(const float4*)(Bptr + (size_t)k0 * SD);
        }
#pragma unroll
        for (int k = 0; k < BK; k++) {
            ulonglong2 bb0 = *(const ulonglong2*)(&Bs[cur][k][tx * 8]);
            ulonglong2 bb1 = *(const ulonglong2*)(&Bs[cur][k][tx * 8 + 4]);
            unsigned long long b2[4] = {bb0.x, bb0.y, bb1.x, bb1.y};
            float4 a0 = *(const float4*)(&As[cur][k][ty * 8]);
            float4 a1 = *(const float4*)(&As[cur][k][ty * 8 + 4]);
            unsigned long long a2[8];
            a2[0] = bcast2(a0.x); a2[1] = bcast2(a0.y); a2[2] = bcast2(a0.z); a2[3] = bcast2(a0.w);
            a2[4] = bcast2(a1.x); a2[5] = bcast2(a1.y); a2[6] = bcast2(a1.z); a2[7] = bcast2(a1.w);
#pragma unroll
            for (int i = 0; i < 8; i++)
#pragma unroll
                for (int j = 0; j < 4; j++)
                    ffma2(acc[i][j], a2[i], b2[j]);
        }
        if (t + 1 < KTILES) {
#pragma unroll
            for (int c = 0; c < 4; c++) {
                As[nxt][c * 4 + 0][tid] = ra[c].x;
                As[nxt][c * 4 + 1][tid] = ra[c].y;
                As[nxt][c * 4 + 2][tid] = ra[c].z;
                As[nxt][c * 4 + 3][tid] = ra[c].w;
            }
            *(float4*)(&Bs[nxt][brow][bcol4 * 4]) = rb;
        }
        __syncthreads();
    }

    int gcol = bn + tx * 8;
#pragma unroll
    for (int i = 0; i < 8; i++) {
        int grow = bm + ty * 8 + i;
        if (grow >= M) continue;
        float2 u0 = unpack2(acc[i][0]);
        float2 u1 = unpack2(acc[i][1]);
        float2 u2 = unpack2(acc[i][2]);
        float2 u3 = unpack2(acc[i][3]);
        float* crow = C + (size_t)grow * SD + gcol;
        if (accumulate) {
            float4 c0 = *(float4*)crow;
            float4 c1 = *(float4*)(crow + 4);
            *(float4*)crow       = make_float4(c0.x + u0.x, c0.y + u0.y, c0.z + u1.x, c0.w + u1.y);
            *(float4*)(crow + 4) = make_float4(c1.x + u2.x, c1.y + u2.y, c1.z + u3.x, c1.w + u3.y);
        } else {
            *(float4*)crow       = make_float4(u0.x, u0.y, u1.x, u1.y);
            *(float4*)(crow + 4) = make_float4(u2.x, u2.y, u3.x, u3.y);
        }
    }
}

// h = emb + relu(h_pre + Bias); pads -> 0.
__global__ void h_kernel(const float* __restrict__ Bias) {
    int i = blockIdx.x * blockDim.x + threadIdx.x;
    if (i >= E_N * SD4) return;
    int j = i % SD4;
    float4 o = make_float4(0.f, 0.f, 0.f, 0.f);
    if (j < D4) {
        float4 p = ((const float4*)g_A1)[i];
        float4 e = ((const float4*)g_emb)[i];
        int d = j * 4;
        o.x = e.x + fmaxf(p.x + Bias[d + 0], 0.f);
        o.y = e.y + fmaxf(p.y + Bias[d + 1], 0.f);
        o.z = e.z + fmaxf(p.z + Bias[d + 2], 0.f);
        o.w = e.w + fmaxf(p.w + Bias[d + 3], 0.f);
    }
    ((float4*)g_A2)[i] = o;
}

// Fused hinge loss: one block per pair t.
__global__ __launch_bounds__(256) void loss_kernel(const int* __restrict__ pl,
                                                   const int* __restrict__ pr,
                                                   const int* __restrict__ nr,
                                                   const int* __restrict__ nl,
                                                   const float* __restrict__ mask,
                                                   const float* __restrict__ node,
                                                   float* __restrict__ out) {
    __shared__ float4 sl[D4], sr[D4];
    __shared__ float wpart[8];
    __shared__ float s_dm;
    int t    = blockIdx.x;
    int tid  = threadIdx.x;
    int lane = tid & 31;
    int wid  = tid >> 5;

    const float4* xl = (const float4*)(node + (size_t)pl[t] * SD);
    const float4* xr = (const float4*)(node + (size_t)pr[t] * SD);
    float d = 0.f;
    if (tid < D4) {
        float4 a = xl[tid], b = xr[tid];
        sl[tid] = a; sr[tid] = b;
        d = fabsf(a.x - b.x) + fabsf(a.y - b.y) + fabsf(a.z - b.z) + fabsf(a.w - b.w);
    }
    d = warp_sum(d);
    if (lane == 0) wpart[wid] = d;
    __syncthreads();
    if (tid == 0) s_dm = wpart[0] + wpart[1] + wpart[2] + GAMMA_F;
    __syncthreads();
    float dm = s_dm;

    float hsum = 0.f;
    for (int k = wid; k < K_N; k += 8) {
        int i = t * K_N + k;
        const float4* xR = (const float4*)(node + (size_t)nr[i] * SD);
        const float4* xL = (const float4*)(node + (size_t)nl[i] * SD);
        float s1 = 0.f, s2 = 0.f;
#pragma unroll
        for (int it = 0; it < 3; it++) {
            int j = lane + it * 32;
            if (j < D4) {
                float4 a = sl[j], b = sr[j], cr = xR[j], cl = xL[j];
                s1 += fabsf(a.x - cr.x) + fabsf(a.y - cr.y) + fabsf(a.z - cr.z) + fabsf(a.w - cr.w);
                s2 += fabsf(cl.x - b.x) + fabsf(cl.y - b.y) + fabsf(cl.z - b.z) + fabsf(cl.w - b.w);
            }
        }
        s1 = warp_sum(s1);
        s2 = warp_sum(s2);
        if (lane == 0) hsum += (fmaxf(dm - s1, 0.f) + fmaxf(dm - s2, 0.f)) * mask[i];
    }
    if (lane == 0) wpart[wid] = hsum;
    __syncthreads();
    if (tid == 0) {
        float tot = 0.f;
#pragma unroll
        for (int w = 0; w < 8; w++) tot += wpart[w];
        atomicAdd(out, tot * 0.5f);
    }
}

// ---------------- host ----------------
extern "C" void kernel_launch(void* const* d_in, const int* in_sizes, int n_in,
                              void* d_out, int out_size) {
    const float* we    = (const float*)d_in[0];
    const float* kgw   = (const float*)d_in[1];
    const float* bg    = (const float*)d_in[2];
    const float* W1    = (const float*)d_in[3];
    const float* W2    = (const float*)d_in[4];
    const float* Dense = (const float*)d_in[5];
    const float* Bias  = (const float*)d_in[6];
    const int*   hr_rows = (const int*)d_in[7];
    const int*   hr_cols = (const int*)d_in[8];
    const float* hr_vals = (const float*)d_in[9];
    const int*   tr_rows = (const int*)d_in[10];
    const int*   tr_cols = (const int*)d_in[11];
    const float* tr_vals = (const float*)d_in[12];
    const int*   er_rows = (const int*)d_in[13];
    const int*   er_cols = (const int*)d_in[14];
    const float* er_vals = (const float*)d_in[15];
    const int*   adj_rows = (const int*)d_in[16];
    const int*   adj_cols = (const int*)d_in[17];
    const float* adj_vals = (const float*)d_in[18];
    const int*   pos_left  = (const int*)d_in[19];
    const int*   pos_right = (const int*)d_in[20];
    const int*   neg_right = (const int*)d_in[21];
    const int*   neg_left  = (const int*)d_in[22];
    const float* mask      = (const float*)d_in[23];
    float* out = (float*)d_out;

    int nnz_hr  = in_sizes[7];
    int nnz_tr  = in_sizes[10];
    int nnz_er  = in_sizes[13];
    int nnz_adj = in_sizes[16];

    float *p_emb, *p_A1, *p_A2, *p_A3, *p_A5, *p_A6, *p_Lm, *p_Rm, *p_P, *p_Wt;
    __nv_bfloat16 *p_Bh, *p_Bl, *p_WTh, *p_WTl;
    cudaGetSymbolAddress((void**)&p_emb, g_emb);
    cudaGetSymbolAddress((void**)&p_A1,  g_A1);
    cudaGetSymbolAddress((void**)&p_A2,  g_A2);
    cudaGetSymbolAddress((void**)&p_A3,  g_A3);
    cudaGetSymbolAddress((void**)&p_A5,  g_A5);
    cudaGetSymbolAddress((void**)&p_A6,  g_A6);
    cudaGetSymbolAddress((void**)&p_Lm,  g_Lm);
    cudaGetSymbolAddress((void**)&p_Rm,  g_Rm);
    cudaGetSymbolAddress((void**)&p_P,   g_P);
    cudaGetSymbolAddress((void**)&p_Wt,  g_Wt);
    cudaGetSymbolAddress((void**)&p_Bh,  g_Bh);
    cudaGetSymbolAddress((void**)&p_Bl,  g_Bl);
    cudaGetSymbolAddress((void**)&p_WTh, g_WTh);
    cudaGetSymbolAddress((void**)&p_WTl, g_WTl);

    cudaFuncSetAttribute(mgemm_kernel, cudaFuncAttributeMaxDynamicSharedMemorySize, MM_SMEM);

    const int ELEM = E_N * SD;
    dim3 mmGrid(5, (E_N + 127) / 128);              // N-tiles fastest -> X-row L2 reuse
    dim3 gemmGridR(SD / BN, (R_N + BM - 1) / BM);   // (5, 4)

    // launches 1-3, then #4 = first HMMA GEMM (profiled by ncu -s 5 -c 1 offset)
    wsplit_kernel<<<(4 * WOFF + 255) / 256, 256>>>(Dense, W1, W2, kgw);
    normalize_kernel<<<(E_N * 32) / 256, 256>>>(we);
    csplit_kernel<<<(E_N * SD4 + 255) / 256, 256>>>(p_emb);
    mgemm_kernel<<<mmGrid, 256, MM_SMEM>>>(p_Bh, p_Bl, p_WTh, p_WTl, p_A1, E_N, 0, 0, 0, 0);

    // relation aggregation
    zero4_kernel<<<(R_N * SD / 4 + 255) / 256, 256>>>((float4*)p_Lm, R_N * SD / 4);
    zero4_kernel<<<(R_N * SD / 4 + 255) / 256, 256>>>((float4*)p_Rm, R_N * SD / 4);
    spmm_kernel<<<(nnz_hr + 7) / 8, 256>>>(hr_rows, hr_cols, hr_vals, nnz_hr, p_emb, p_Lm, 0);
    spmm_kernel<<<(nnz_tr + 7) / 8, 256>>>(tr_rows, tr_cols, tr_vals, nnz_tr, p_emb, p_Rm, 0);

    // P = L @ Db1 + Rm @ Db2
    pad_weights_kernel<<<(2 * SD * SD + 255) / 256, 256>>>(Dense);
    sgemm_kernel<<<gemmGridR, 256>>>(p_Lm, p_Wt, p_P, R_N, 0);
    sgemm_kernel<<<gemmGridR, 256>>>(p_Rm, p_Wt + SD * SD, p_P, R_N, 1);

    // h_pre += spmm(er, +-P)
    spmm_kernel<<<(nnz_er + 7) / 8, 256>>>(er_rows, er_cols, er_vals, nnz_er, p_P, p_A1, 1);

    zero_out_kernel<<<1, 1>>>(out);

    // h = emb + relu(h_pre + Bias)
    h_kernel<<<(E_N * SD4 + 255) / 256, 256>>>(Bias);

    // layer 1: t1 = h@W1 -> A3; gcn1 -> A5; gate GEMM (KG) fuses highway -> A6
    csplit_kernel<<<(E_N * SD4 + 255) / 256, 256>>>(p_A2);
    mgemm_kernel<<<mmGrid, 256, MM_SMEM>>>(p_Bh, p_Bl, p_WTh + 1 * WOFF, p_WTl + 1 * WOFF, p_A3, E_N, 0, 0, 0, 0);
    zero4_kernel<<<(ELEM / 4 + 255) / 256, 256>>>((float4*)p_A5, ELEM / 4);
    spmm_kernel<<<(nnz_adj + 7) / 8, 256>>>(adj_rows, adj_cols, adj_vals, nnz_adj, p_A3, p_A5, 0);
    mgemm_kernel<<<mmGrid, 256, MM_SMEM>>>(p_Bh, p_Bl, p_WTh + 3 * WOFF, p_WTl + 3 * WOFF, p_A6, E_N, 3, p_A2, p_A5, bg);

    // layer 2: t2 = hg1@W2 -> A3; gcn2 -> A1; gate GEMM (KG) fuses highway -> node (A2)
    csplit_kernel<<<(E_N * SD4 + 255) / 256, 256>>>(p_A6);
    mgemm_kernel<<<mmGrid, 256, MM_SMEM>>>(p_Bh, p_Bl, p_WTh + 2 * WOFF, p_WTl + 2 * WOFF, p_A3, E_N, 0, 0, 0, 0);
    zero4_kernel<<<(ELEM / 4 + 255) / 256, 256>>>((float4*)p_A1, ELEM / 4);
    spmm_kernel<<<(nnz_adj + 7) / 8, 256>>>(adj_rows, adj_cols, adj_vals, nnz_adj, p_A3, p_A1, 0);
    mgemm_kernel<<<mmGrid, 256, MM_SMEM>>>(p_Bh, p_Bl, p_WTh + 3 * WOFF, p_WTl + 3 * WOFF, p_A2, E_N, 3, p_A6, p_A1, bg);

    // fused loss
    loss_kernel<<<T_N, 256>>>(pos_left, pos_right, neg_right, neg_left, mask, p_A2, out);
    (void)n_in; (void)out_size;
}

// round 11
// speedup vs baseline: 1.7806x; 1.0766x over previous
#include <cuda_runtime.h>
#include <cuda_bf16.h>
#include <math.h>
#include <stdint.h>

#define E_N 100000
#define D_N 300
#define R_N 1000
#define T_N 10000
#define K_N 25
#define SD  320
#define D4  75
#define SD4 80
#define GAMMA_F 1.0f
#define WOFF (320*320)

// ---------------- scratch (device globals: allocation-free) ----------------
__device__ float g_emb[(size_t)E_N * SD];
__device__ float g_A1 [(size_t)E_N * SD];
__device__ float g_A2 [(size_t)E_N * SD];
__device__ float g_A3 [(size_t)E_N * SD];
__device__ float g_A5 [(size_t)E_N * SD];
__device__ float g_A6 [(size_t)E_N * SD];
__device__ float g_Lm [R_N * SD];
__device__ float g_Rm [R_N * SD];
__device__ float g_P  [R_N * SD];
__device__ float g_Wt [2 * SD * SD];
__device__ __nv_bfloat16 g_Bh[(size_t)E_N * SD];  // split pair A (emb, then hg1)
__device__ __nv_bfloat16 g_Bl[(size_t)E_N * SD];
__device__ __nv_bfloat16 g_Ch[(size_t)E_N * SD];  // split pair B (h)
__device__ __nv_bfloat16 g_Cl[(size_t)E_N * SD];
__device__ __nv_bfloat16 g_WTh[4 * WOFF];         // transposed weights hi: 0:Dt 1:W1 2:W2 3:KG
__device__ __nv_bfloat16 g_WTl[4 * WOFF];

// ---------------- helpers ----------------
__device__ __forceinline__ uint32_t smem_to_u32(const void* p) {
    uint32_t a;
    asm("{ .reg .u64 t; cvta.to.shared.u64 t, %1; cvt.u32.u64 %0, t; }" : "=r"(a) : "l"(p));
    return a;
}
__device__ __forceinline__ float warp_sum(float v) {
#pragma unroll
    for (int o = 16; o > 0; o >>= 1) v += __shfl_xor_sync(0xffffffffu, v, o);
    return v;
}
__device__ __forceinline__ unsigned long long bcast2(float x) {
    unsigned long long r;
    asm("mov.b64 %0, {%1, %1};" : "=l"(r) : "f"(x));
    return r;
}
__device__ __forceinline__ float2 unpack2(unsigned long long v) {
    float2 f;
    asm("mov.b64 {%0, %1}, %2;" : "=f"(f.x), "=f"(f.y) : "l"(v));
    return f;
}
__device__ __forceinline__ void ffma2(unsigned long long& d, unsigned long long a, unsigned long long b) {
    asm("fma.rn.f32x2 %0, %1, %2, %0;" : "+l"(d) : "l"(a), "l"(b));
}
__device__ __forceinline__ void red_add_v4(float* p, float a, float b, float c, float d) {
    asm volatile("red.global.add.v4.f32 [%0], {%1, %2, %3, %4};"
                 :: "l"(p), "f"(a), "f"(b), "f"(c), "f"(d) : "memory");
}
__device__ __forceinline__ void cp16(uint32_t dst, const void* src, int src_bytes) {
    asm volatile("cp.async.cg.shared.global [%0], [%1], 16, %2;"
                 :: "r"(dst), "l"(src), "r"(src_bytes) : "memory");
}
#define CP_COMMIT() asm volatile("cp.async.commit_group;" ::: "memory")
template <int N>
__device__ __forceinline__ void cp_wait() {
    asm volatile("cp.async.wait_group %0;" :: "n"(N) : "memory");
}
__device__ __forceinline__ void ldsm4(uint32_t* r, uint32_t addr) {
    asm volatile("ldmatrix.sync.aligned.m8n8.x4.shared.b16 {%0,%1,%2,%3}, [%4];"
                 : "=r"(r[0]), "=r"(r[1]), "=r"(r[2]), "=r"(r[3]) : "r"(addr));
}
__device__ __forceinline__ void mma16816(float* d, const uint32_t* a, uint32_t b0, uint32_t b1) {
    asm volatile("mma.sync.aligned.m16n8k16.row.col.f32.bf16.bf16.f32 "
                 "{%0,%1,%2,%3}, {%4,%5,%6,%7}, {%8,%9}, {%0,%1,%2,%3};"
                 : "+f"(d[0]), "+f"(d[1]), "+f"(d[2]), "+f"(d[3])
                 : "r"(a[0]), "r"(a[1]), "r"(a[2]), "r"(a[3]), "r"(b0), "r"(b1));
}
__device__ __forceinline__ void split2(float v, __nv_bfloat16& h, __nv_bfloat16& l) {
    h = __float2bfloat16_rn(v);
    l = __float2bfloat16_rn(v - __bfloat162float(h));
}

// ---------------- small kernels ----------------
__global__ void zero_out_kernel(float* out) { if (threadIdx.x == 0 && blockIdx.x == 0) out[0] = 0.0f; }

__global__ void zero4_kernel(float4* p, int n4) {
    int i = blockIdx.x * blockDim.x + threadIdx.x;
    if (i < n4) p[i] = make_float4(0.f, 0.f, 0.f, 0.f);
}

__global__ void pad_weights_kernel(const float* __restrict__ Dense) {
    int idx = blockIdx.x * blockDim.x + threadIdx.x;
    if (idx >= 2 * SD * SD) return;
    int w = idx / (SD * SD);
    int rem = idx % (SD * SD);
    int r = rem / SD, c = rem % SD;
    float v = 0.f;
    if (r < D_N && c < D_N) v = Dense[(size_t)(D_N * (1 + w) + r) * D_N + c];
    g_Wt[idx] = v;
}

__global__ void wsplit_kernel(const float* __restrict__ Dense, const float* __restrict__ W1,
                              const float* __restrict__ W2, const float* __restrict__ KG) {
    int idx = blockIdx.x * blockDim.x + threadIdx.x;
    if (idx >= 4 * WOFF) return;
    int w = idx / WOFF;
    int rem = idx % WOFF;
    int n = rem / 320, k = rem % 320;
    float v = 0.f;
    if (n < D_N && k < D_N) {
        const float* src = (w == 0) ? Dense : (w == 1) ? W1 : (w == 2) ? W2 : KG;
        v = src[(size_t)k * D_N + n];
    }
    __nv_bfloat16 hi, lo;
    split2(v, hi, lo);
    g_WTh[idx] = hi;
    g_WTl[idx] = lo;
}

// normalize + emb splits (to Bh/Bl). Warp per row.
__global__ void normalize_kernel(const float* __restrict__ we) {
    int warp = (blockIdx.x * blockDim.x + threadIdx.x) >> 5;
    int lane = threadIdx.x & 31;
    if (warp >= E_N) return;
    const float4* src = (const float4*)(we + (size_t)warp * D_N);
    float4 v[3];
    float s = 0.f;
#pragma unroll
    for (int it = 0; it < 3; it++) {
        int j = lane + it * 32;
        if (j < D4) {
            float4 x = src[j];
            v[it] = x;
            s += x.x * x.x + x.y * x.y + x.z * x.z + x.w * x.w;
        } else v[it] = make_float4(0.f, 0.f, 0.f, 0.f);
    }
    s = warp_sum(s);
    float inv = 1.0f / sqrtf(s);
    float4* dst = (float4*)(g_emb + (size_t)warp * SD);
    __nv_bfloat162* bh = (__nv_bfloat162*)(g_Bh + (size_t)warp * SD);
    __nv_bfloat162* bl = (__nv_bfloat162*)(g_Bl + (size_t)warp * SD);
#pragma unroll
    for (int it = 0; it < 3; it++) {
        int j = lane + it * 32;
        if (j < SD4) {
            float4 o = make_float4(0.f, 0.f, 0.f, 0.f);
            if (j < D4) o = make_float4(v[it].x * inv, v[it].y * inv, v[it].z * inv, v[it].w * inv);
            dst[j] = o;
            float xs[4] = {o.x, o.y, o.z, o.w};
            __nv_bfloat16 h[4], l[4];
#pragma unroll
            for (int q = 0; q < 4; q++) split2(xs[q], h[q], l[q]);
            __nv_bfloat162 h0, h1, l0, l1;
            h0.x = h[0]; h0.y = h[1]; h1.x = h[2]; h1.y = h[3];
            l0.x = l[0]; l0.y = l[1]; l1.x = l[2]; l1.y = l[3];
            bh[2 * j] = h0; bh[2 * j + 1] = h1;
            bl[2 * j] = l0; bl[2 * j + 1] = l1;
        }
    }
}

// COO SpMM scatter with vector reductions. Warp per nnz.
__global__ void spmm_kernel(const int* __restrict__ rows, const int* __restrict__ cols,
                            const float* __restrict__ vals, int nnz,
                            const float* __restrict__ X, float* __restrict__ Out,
                            int rel_mode) {
    int warp = (blockIdx.x * blockDim.x + threadIdx.x) >> 5;
    int lane = threadIdx.x & 31;
    if (warp >= nnz) return;
    int   r = rows[warp];
    int   c = cols[warp];
    float v = vals[warp];
    if (rel_mode && c >= R_N) { c -= R_N; v = -v; }
    const float4* xr = (const float4*)(X + (size_t)c * SD);
    float* orow = Out + (size_t)r * SD;
#pragma unroll
    for (int it = 0; it < 3; it++) {
        int j = lane + it * 32;
        if (j < D4) {
            float4 x = xr[j];
            red_add_v4(orow + j * 4, v * x.x, v * x.y, v * x.z, v * x.w);
        }
    }
}

// ---------------- HMMA GEMM (bf16 split-2): C[M,320] = X @ W ----------------
// Block 128m x 64n, 8 warps (2m x 4n). K-chunk 32, double buffered, 3 CTAs/SM.
// mode 0: store fp32; mode 3: highway epilogue; mode 4: highway + write bf16 splits to Oh/Ol.
#define MMK 32
#define MMS 40                         // smem row stride bf16 (32 + 8 pad)
#define A_TB (128 * MMS * 2)           // 10240 B
#define B_TB (64 * MMS * 2)            // 5120 B
#define MM_STAGE (2 * A_TB + 2 * B_TB) // 30720 B
#define MM_SMEM  (2 * MM_STAGE)        // 61440 B
#define MM_CH 10                       // 320 / 32

__device__ __forceinline__ void mm_load_stage(uint32_t sb,
                                              const __nv_bfloat16* Xh, const __nv_bfloat16* Xl,
                                              const __nv_bfloat16* Wh, const __nv_bfloat16* Wl,
                                              int bm, int bn, int M, int k0, int tid) {
#pragma unroll
    for (int q = 0; q < 6; q++) {
        int idx = q * 256 + tid;
        if (idx < 1024) {
            int part = idx >> 9;               // 0: Ah, 1: Al
            int r = (idx & 511) >> 2, c = idx & 3;
            const __nv_bfloat16* src = (part ? Xl : Xh) + (size_t)(bm + r) * 320 + k0 + c * 8;
            int ok = (bm + r < M) ? 16 : 0;
            cp16(sb + part * A_TB + r * (MMS * 2) + c * 16, src, ok);
        } else {
            int t = idx - 1024;
            int part = t >> 8;                 // 0: Bh, 1: Bl
            int rr = t & 255;
            int r = rr >> 2, c = rr & 3;
            const __nv_bfloat16* src = (part ? Wl : Wh) + (size_t)(bn + r) * 320 + k0 + c * 8;
            cp16(sb + 2 * A_TB + part * B_TB + r * (MMS * 2) + c * 16, src, 16);
        }
    }
    CP_COMMIT();
}

__global__ __launch_bounds__(256, 3) void mgemm_kernel(const __nv_bfloat16* __restrict__ Xh,
                                                       const __nv_bfloat16* __restrict__ Xl,
                                                       const __nv_bfloat16* __restrict__ Wh,
                                                       const __nv_bfloat16* __restrict__ Wl,
                                                       float* __restrict__ C, int M, int mode,
                                                       const float* __restrict__ ep1,
                                                       const float* __restrict__ ep2,
                                                       const float* __restrict__ epv,
                                                       __nv_bfloat16* __restrict__ Oh,
                                                       __nv_bfloat16* __restrict__ Ol) {
    extern __shared__ char sm8[];
    uint32_t smb = smem_to_u32(sm8);
    int tid = threadIdx.x, wid = tid >> 5, lane = tid & 31;
    int bn = blockIdx.x * 64, bm = blockIdx.y * 128;
    int wm = (wid >> 2) * 64;
    int wn = (wid & 3) * 16;

    float acc[4][2][4];
#pragma unroll
    for (int i = 0; i < 4; i++)
#pragma unroll
        for (int j = 0; j < 2; j++)
#pragma unroll
            for (int q = 0; q < 4; q++) acc[i][j][q] = 0.f;

    int aRow = lane & 15, aKsel = (lane >> 4) * 8;
    int bRow = (lane >> 4) * 8 + (lane & 7), bKsel = ((lane >> 3) & 1) * 8;

    mm_load_stage(smb, Xh, Xl, Wh, Wl, bm, bn, M, 0, tid);

    for (int ch = 0; ch < MM_CH; ch++) {
        uint32_t sb = smb + (ch & 1) * MM_STAGE;
        if (ch + 1 < MM_CH)
            mm_load_stage(smb + ((ch + 1) & 1) * MM_STAGE, Xh, Xl, Wh, Wl, bm, bn, M, (ch + 1) * MMK, tid);
        if (ch + 1 < MM_CH) cp_wait<1>(); else cp_wait<0>();
        __syncthreads();
#pragma unroll
        for (int ks = 0; ks < 2; ks++) {
            int k0 = ks * 16;
            uint32_t ah[4][4], al[4][4], bh[4], bl[4];
#pragma unroll
            for (int i = 0; i < 4; i++) {
                uint32_t ad = sb + ((wm + i * 16 + aRow) * MMS + k0 + aKsel) * 2;
                ldsm4(ah[i], ad);
                ldsm4(al[i], ad + A_TB);
            }
            uint32_t bd = sb + 2 * A_TB + ((wn + bRow) * MMS + k0 + bKsel) * 2;
            ldsm4(bh, bd);
            ldsm4(bl, bd + B_TB);
#pragma unroll
            for (int i = 0; i < 4; i++)
#pragma unroll
                for (int j = 0; j < 2; j++) {
                    mma16816(acc[i][j], ah[i], bh[j * 2], bh[j * 2 + 1]);
                    mma16816(acc[i][j], ah[i], bl[j * 2], bl[j * 2 + 1]);
                    mma16816(acc[i][j], al[i], bh[j * 2], bh[j * 2 + 1]);
                }
        }
        __syncthreads();
    }

    // epilogue
#pragma unroll
    for (int i = 0; i < 4; i++)
#pragma unroll
        for (int j = 0; j < 2; j++) {
            int col = bn + wn + j * 8 + (lane & 3) * 2;
#pragma unroll
            for (int half = 0; half < 2; half++) {
                int row = bm + wm + i * 16 + (lane >> 2) + half * 8;
                if (row >= M) continue;
                float v0 = acc[i][j][half * 2], v1 = acc[i][j][half * 2 + 1];
                float* crow = C + (size_t)row * SD + col;
                if (mode == 0) {
                    *(float2*)crow = make_float2(v0, v1);
                } else {
                    const float* l1 = ep1 + (size_t)row * SD + col;
                    const float* gc = ep2 + (size_t)row * SD + col;
                    float2 a = *(const float2*)l1;
                    float2 g = *(const float2*)gc;
                    float o0 = 0.f, o1 = 0.f;
                    if (col < D_N) {
                        float tg = 1.0f / (1.0f + expf(-(v0 + epv[col])));
                        o0 = tg * fmaxf(g.x, 0.f) + (1.0f - tg) * a.x;
                    }
                    if (col + 1 < D_N) {
                        float tg = 1.0f / (1.0f + expf(-(v1 + epv[col + 1])));
                        o1 = tg * fmaxf(g.y, 0.f) + (1.0f - tg) * a.y;
                    }
                    *(float2*)crow = make_float2(o0, o1);
                    if (mode == 4) {
                        __nv_bfloat16 h0, h1, l0, l1b;
                        split2(o0, h0, l0);
                        split2(o1, h1, l1b);
                        __nv_bfloat162 hh, ll;
                        hh.x = h0; hh.y = h1;
                        ll.x = l0; ll.y = l1b;
                        *(__nv_bfloat162*)(Oh + (size_t)row * SD + col) = hh;
                        *(__nv_bfloat162*)(Ol + (size_t)row * SD + col) = ll;
                    }
                }
            }
        }
}

// ---------------- FFMA2 SGEMM (small R_N GEMMs) ----------------
#define BM 256
#define BN 64
#define BK 16
#define KTILES 19
__global__ __launch_bounds__(256, 2) void sgemm_kernel(const float* __restrict__ A,
                                                       const float* __restrict__ B,
                                                       float* __restrict__ C,
                                                       int M, int accumulate) {
    __shared__ float As[2][BK][BM];
    __shared__ float Bs[2][BK][BN];
    int bm = blockIdx.y * BM;
    int bn = blockIdx.x * BN;
    int tid = threadIdx.x;
    int tx = tid & 7;
    int ty = tid >> 3;
    int arow = bm + tid;
    bool avalid = arow < M;
    const float* Aptr = A + (size_t)arow * SD;
    int brow  = tid >> 4;
    int bcol4 = tid & 15;
    const float* Bptr = B + (size_t)brow * SD + bn + bcol4 * 4;

    unsigned long long acc[8][4];
#pragma unroll
    for (int i = 0; i < 8; i++)
#pragma unroll
        for (int j = 0; j < 4; j++) acc[i][j] = 0ull;

    float4 ra[4], rb;
#pragma unroll
    for (int c = 0; c < 4; c++)
        ra[c] = avalid ? *(const float4*)(Aptr + c * 4) : make_float4(0.f, 0.f, 0.f, 0.f);
    rb = *(const float4*)(Bptr);
#pragma unroll
    for (int c = 0; c < 4; c++) {
        As[0][c * 4 + 0][tid] = ra[c].x;
        As[0][c * 4 + 1][tid] = ra[c].y;
        As[0][c * 4 + 2][tid] = ra[c].z;
        As[0][c * 4 + 3][tid] = ra[c].w;
    }
    *(float4*)(&Bs[0][brow][bcol4 * 4]) = rb;
    __syncthreads();

    for (int t = 0; t < KTILES; t++) {
        int cur = t & 1, nxt = cur ^ 1;
        if (t + 1 < KTILES) {
            int k0 = (t + 1) * BK;
#pragma unroll
            for (int c = 0; c < 4; c++)
                ra[c] = avalid ? *(const float4*)(Aptr + k0 + c * 4) : make_float4(0.f, 0.f, 0.f, 0.f);
            rb = *(const float4*)(Bptr + (size_t)k0 * SD);
        }
#pragma unroll
        for (int k = 0; k < BK; k++) {
            ulonglong2 bb0 = *(const ulonglong2*)(&Bs[cur][k][tx * 8]);
            ulonglong2 bb1 = *(const ulonglong2*)(&Bs[cur][k][tx * 8 + 4]);
            unsigned long long b2[4] = {bb0.x, bb0.y, bb1.x, bb1.y};
            float4 a0 = *(const float4*)(&As[cur][k][ty * 8]);
            float4 a1 = *(const float4*)(&As[cur][k][ty * 8 + 4]);
            unsigned long long a2[8];
            a2[0] = bcast2(a0.x); a2[1] = bcast2(a0.y); a2[2] = bcast2(a0.z); a2[3] = bcast2(a0.w);
            a2[4] = bcast2(a1.x); a2[5] = bcast2(a1.y); a2[6] = bcast2(a1.z); a2[7] = bcast2(a1.w);
#pragma unroll
            for (int i = 0; i < 8; i++)
#pragma unroll
                for (int j = 0; j < 4; j++)
                    ffma2(acc[i][j], a2[i], b2[j]);
        }
        if (t + 1 < KTILES) {
#pragma unroll
            for (int c = 0; c < 4; c++) {
                As[nxt][c * 4 + 0][tid] = ra[c].x;
                As[nxt][c * 4 + 1][tid] = ra[c].y;
                As[nxt][c * 4 + 2][tid] = ra[c].z;
                As[nxt][c * 4 + 3][tid] = ra[c].w;
            }
            *(float4*)(&Bs[nxt][brow][bcol4 * 4]) = rb;
        }
        __syncthreads();
    }

    int gcol = bn + tx * 8;
#pragma unroll
    for (int i = 0; i < 8; i++) {
        int grow = bm + ty * 8 + i;
        if (grow >= M) continue;
        float2 u0 = unpack2(acc[i][0]);
        float2 u1 = unpack2(acc[i][1]);
        float2 u2 = unpack2(acc[i][2]);
        float2 u3 = unpack2(acc[i][3]);
        float* crow = C + (size_t)grow * SD + gcol;
        if (accumulate) {
            float4 c0 = *(float4*)crow;
            float4 c1 = *(float4*)(crow + 4);
            *(float4*)crow       = make_float4(c0.x + u0.x, c0.y + u0.y, c0.z + u1.x, c0.w + u1.y);
            *(float4*)(crow + 4) = make_float4(c1.x + u2.x, c1.y + u2.y, c1.z + u3.x, c1.w + u3.y);
        } else {
            *(float4*)crow       = make_float4(u0.x, u0.y, u1.x, u1.y);
            *(float4*)(crow + 4) = make_float4(u2.x, u2.y, u3.x, u3.y);
        }
    }
}

// h = emb + relu(h_pre + Bias); pads -> 0; also writes h splits to Ch/Cl.
__global__ void h_kernel(const float* __restrict__ Bias) {
    int i = blockIdx.x * blockDim.x + threadIdx.x;   // float4 index
    if (i >= E_N * SD4) return;
    int j = i % SD4;
    float4 o = make_float4(0.f, 0.f, 0.f, 0.f);
    if (j < D4) {
        float4 p = ((const float4*)g_A1)[i];
        float4 e = ((const float4*)g_emb)[i];
        int d = j * 4;
        o.x = e.x + fmaxf(p.x + Bias[d + 0], 0.f);
        o.y = e.y + fmaxf(p.y + Bias[d + 1], 0.f);
        o.z = e.z + fmaxf(p.z + Bias[d + 2], 0.f);
        o.w = e.w + fmaxf(p.w + Bias[d + 3], 0.f);
    }
    ((float4*)g_A2)[i] = o;
    float xs[4] = {o.x, o.y, o.z, o.w};
    __nv_bfloat16 h[4], l[4];
#pragma unroll
    for (int q = 0; q < 4; q++) split2(xs[q], h[q], l[q]);
    __nv_bfloat162 h0, h1, l0, l1;
    h0.x = h[0]; h0.y = h[1]; h1.x = h[2]; h1.y = h[3];
    l0.x = l[0]; l0.y = l[1]; l1.x = l[2]; l1.y = l[3];
    ((__nv_bfloat162*)g_Ch)[2 * i]     = h0;
    ((__nv_bfloat162*)g_Ch)[2 * i + 1] = h1;
    ((__nv_bfloat162*)g_Cl)[2 * i]     = l0;
    ((__nv_bfloat162*)g_Cl)[2 * i + 1] = l1;
}

// Fused hinge loss: one block per pair t.
__global__ __launch_bounds__(256) void loss_kernel(const int* __restrict__ pl,
                                                   const int* __restrict__ pr,
                                                   const int* __restrict__ nr,
                                                   const int* __restrict__ nl,
                                                   const float* __restrict__ mask,
                                                   const float* __restrict__ node,
                                                   float* __restrict__ out) {
    __shared__ float4 sl[D4], sr[D4];
    __shared__ float wpart[8];
    __shared__ float s_dm;
    int t    = blockIdx.x;
    int tid  = threadIdx.x;
    int lane = tid & 31;
    int wid  = tid >> 5;

    const float4* xl = (const float4*)(node + (size_t)pl[t] * SD);
    const float4* xr = (const float4*)(node + (size_t)pr[t] * SD);
    float d = 0.f;
    if (tid < D4) {
        float4 a = xl[tid], b = xr[tid];
        sl[tid] = a; sr[tid] = b;
        d = fabsf(a.x - b.x) + fabsf(a.y - b.y) + fabsf(a.z - b.z) + fabsf(a.w - b.w);
    }
    d = warp_sum(d);
    if (lane == 0) wpart[wid] = d;
    __syncthreads();
    if (tid == 0) s_dm = wpart[0] + wpart[1] + wpart[2] + GAMMA_F;
    __syncthreads();
    float dm = s_dm;

    float hsum = 0.f;
    for (int k = wid; k < K_N; k += 8) {
        int i = t * K_N + k;
        const float4* xR = (const float4*)(node + (size_t)nr[i] * SD);
        const float4* xL = (const float4*)(node + (size_t)nl[i] * SD);
        float s1 = 0.f, s2 = 0.f;
#pragma unroll
        for (int it = 0; it < 3; it++) {
            int j = lane + it * 32;
            if (j < D4) {
                float4 a = sl[j], b = sr[j], cr = xR[j], cl = xL[j];
                s1 += fabsf(a.x - cr.x) + fabsf(a.y - cr.y) + fabsf(a.z - cr.z) + fabsf(a.w - cr.w);
                s2 += fabsf(cl.x - b.x) + fabsf(cl.y - b.y) + fabsf(cl.z - b.z) + fabsf(cl.w - b.w);
            }
        }
        s1 = warp_sum(s1);
        s2 = warp_sum(s2);
        if (lane == 0) hsum += (fmaxf(dm - s1, 0.f) + fmaxf(dm - s2, 0.f)) * mask[i];
    }
    if (lane == 0) wpart[wid] = hsum;
    __syncthreads();
    if (tid == 0) {
        float tot = 0.f;
#pragma unroll
        for (int w = 0; w < 8; w++) tot += wpart[w];
        atomicAdd(out, tot * 0.5f);
    }
}

// ---------------- host ----------------
extern "C" void kernel_launch(void* const* d_in, const int* in_sizes, int n_in,
                              void* d_out, int out_size) {
    const float* we    = (const float*)d_in[0];
    const float* kgw   = (const float*)d_in[1];
    const float* bg    = (const float*)d_in[2];
    const float* W1    = (const float*)d_in[3];
    const float* W2    = (const float*)d_in[4];
    const float* Dense = (const float*)d_in[5];
    const float* Bias  = (const float*)d_in[6];
    const int*   hr_rows = (const int*)d_in[7];
    const int*   hr_cols = (const int*)d_in[8];
    const float* hr_vals = (const float*)d_in[9];
    const int*   tr_rows = (const int*)d_in[10];
    const int*   tr_cols = (const int*)d_in[11];
    const float* tr_vals = (const float*)d_in[12];
    const int*   er_rows = (const int*)d_in[13];
    const int*   er_cols = (const int*)d_in[14];
    const float* er_vals = (const float*)d_in[15];
    const int*   adj_rows = (const int*)d_in[16];
    const int*   adj_cols = (const int*)d_in[17];
    const float* adj_vals = (const float*)d_in[18];
    const int*   pos_left  = (const int*)d_in[19];
    const int*   pos_right = (const int*)d_in[20];
    const int*   neg_right = (const int*)d_in[21];
    const int*   neg_left  = (const int*)d_in[22];
    const float* mask      = (const float*)d_in[23];
    float* out = (float*)d_out;

    int nnz_hr  = in_sizes[7];
    int nnz_tr  = in_sizes[10];
    int nnz_er  = in_sizes[13];
    int nnz_adj = in_sizes[16];

    float *p_emb, *p_A1, *p_A2, *p_A3, *p_A5, *p_A6, *p_Lm, *p_Rm, *p_P, *p_Wt;
    __nv_bfloat16 *p_Bh, *p_Bl, *p_Ch, *p_Cl, *p_WTh, *p_WTl;
    cudaGetSymbolAddress((void**)&p_emb, g_emb);
    cudaGetSymbolAddress((void**)&p_A1,  g_A1);
    cudaGetSymbolAddress((void**)&p_A2,  g_A2);
    cudaGetSymbolAddress((void**)&p_A3,  g_A3);
    cudaGetSymbolAddress((void**)&p_A5,  g_A5);
    cudaGetSymbolAddress((void**)&p_A6,  g_A6);
    cudaGetSymbolAddress((void**)&p_Lm,  g_Lm);
    cudaGetSymbolAddress((void**)&p_Rm,  g_Rm);
    cudaGetSymbolAddress((void**)&p_P,   g_P);
    cudaGetSymbolAddress((void**)&p_Wt,  g_Wt);
    cudaGetSymbolAddress((void**)&p_Bh,  g_Bh);
    cudaGetSymbolAddress((void**)&p_Bl,  g_Bl);
    cudaGetSymbolAddress((void**)&p_Ch,  g_Ch);
    cudaGetSymbolAddress((void**)&p_Cl,  g_Cl);
    cudaGetSymbolAddress((void**)&p_WTh, g_WTh);
    cudaGetSymbolAddress((void**)&p_WTl, g_WTl);

    cudaFuncSetAttribute(mgemm_kernel, cudaFuncAttributeMaxDynamicSharedMemorySize, MM_SMEM);

    const int ELEM = E_N * SD;
    dim3 mmGrid(5, (E_N + 127) / 128);
    dim3 gemmGridR(SD / BN, (R_N + BM - 1) / BM);

    // 1-3, then launch #4 = first HMMA GEMM (profiled)
    wsplit_kernel<<<(4 * WOFF + 255) / 256, 256>>>(Dense, W1, W2, kgw);
    normalize_kernel<<<(E_N * 32) / 256, 256>>>(we);
    zero4_kernel<<<(R_N * SD / 4 + 255) / 256, 256>>>((float4*)p_Lm, R_N * SD / 4);
    mgemm_kernel<<<mmGrid, 256, MM_SMEM>>>(p_Bh, p_Bl, p_WTh, p_WTl, p_A1, E_N, 0, 0, 0, 0, 0, 0);

    // relation aggregation
    zero4_kernel<<<(R_N * SD / 4 + 255) / 256, 256>>>((float4*)p_Rm, R_N * SD / 4);
    spmm_kernel<<<(nnz_hr + 7) / 8, 256>>>(hr_rows, hr_cols, hr_vals, nnz_hr, p_emb, p_Lm, 0);
    spmm_kernel<<<(nnz_tr + 7) / 8, 256>>>(tr_rows, tr_cols, tr_vals, nnz_tr, p_emb, p_Rm, 0);

    // P = L @ Db1 + Rm @ Db2
    pad_weights_kernel<<<(2 * SD * SD + 255) / 256, 256>>>(Dense);
    sgemm_kernel<<<gemmGridR, 256>>>(p_Lm, p_Wt, p_P, R_N, 0);
    sgemm_kernel<<<gemmGridR, 256>>>(p_Rm, p_Wt + SD * SD, p_P, R_N, 1);

    // h_pre += spmm(er, +-P)
    spmm_kernel<<<(nnz_er + 7) / 8, 256>>>(er_rows, er_cols, er_vals, nnz_er, p_P, p_A1, 1);

    zero_out_kernel<<<1, 1>>>(out);

    // h = emb + relu(h_pre + Bias)  (+ h splits -> Ch/Cl)
    h_kernel<<<(E_N * SD4 + 255) / 256, 256>>>(Bias);

    // layer 1: t1 = h@W1 -> A3; gcn1 -> A5; gate GEMM fuses highway -> A6 (+ hg1 splits -> Bh/Bl)
    mgemm_kernel<<<mmGrid, 256, MM_SMEM>>>(p_Ch, p_Cl, p_WTh + 1 * WOFF, p_WTl + 1 * WOFF, p_A3, E_N, 0, 0, 0, 0, 0, 0);
    zero4_kernel<<<(ELEM / 4 + 255) / 256, 256>>>((float4*)p_A5, ELEM / 4);
    spmm_kernel<<<(nnz_adj + 7) / 8, 256>>>(adj_rows, adj_cols, adj_vals, nnz_adj, p_A3, p_A5, 0);
    mgemm_kernel<<<mmGrid, 256, MM_SMEM>>>(p_Ch, p_Cl, p_WTh + 3 * WOFF, p_WTl + 3 * WOFF, p_A6, E_N, 4, p_A2, p_A5, bg, p_Bh, p_Bl);

    // layer 2: t2 = hg1@W2 -> A3; gcn2 -> A1; gate GEMM fuses highway -> node (A2)
    mgemm_kernel<<<mmGrid, 256, MM_SMEM>>>(p_Bh, p_Bl, p_WTh + 2 * WOFF, p_WTl + 2 * WOFF, p_A3, E_N, 0, 0, 0, 0, 0, 0);
    zero4_kernel<<<(ELEM / 4 + 255) / 256, 256>>>((float4*)p_A1, ELEM / 4);
    spmm_kernel<<<(nnz_adj + 7) / 8, 256>>>(adj_rows, adj_cols, adj_vals, nnz_adj, p_A3, p_A1, 0);
    mgemm_kernel<<<mmGrid, 256, MM_SMEM>>>(p_Bh, p_Bl, p_WTh + 3 * WOFF, p_WTl + 3 * WOFF, p_A2, E_N, 3, p_A6, p_A1, bg, 0, 0);

    // fused loss
    loss_kernel<<<T_N, 256>>>(pos_left, pos_right, neg_right, neg_left, mask, p_A2, out);
    (void)n_in; (void)out_size;
}

// round 12
// speedup vs baseline: 1.7948x; 1.0080x over previous
#include <cuda_runtime.h>
#include <cuda_bf16.h>
#include <math.h>
#include <stdint.h>

#define E_N 100000
#define D_N 300
#define R_N 1000
#define T_N 10000
#define K_N 25
#define SD  320
#define D4  75
#define SD4 80
#define GAMMA_F 1.0f
#define WOFF (320*320)

// ---------------- scratch (device globals: allocation-free) ----------------
__device__ float g_emb[(size_t)E_N * SD];
__device__ float g_A1 [(size_t)E_N * SD];
__device__ float g_A2 [(size_t)E_N * SD];
__device__ float g_A3 [(size_t)E_N * SD];
__device__ float g_A5 [(size_t)E_N * SD];
__device__ float g_A6 [(size_t)E_N * SD];
__device__ float g_Lm [R_N * SD];
__device__ float g_Rm [R_N * SD];
__device__ float g_P  [R_N * SD];
__device__ float g_Wt [2 * SD * SD];
__device__ __nv_bfloat16 g_Bh[(size_t)E_N * SD];  // split pair A (emb, then hg1)
__device__ __nv_bfloat16 g_Bl[(size_t)E_N * SD];
__device__ __nv_bfloat16 g_Ch[(size_t)E_N * SD];  // split pair B (h)
__device__ __nv_bfloat16 g_Cl[(size_t)E_N * SD];
__device__ __nv_bfloat16 g_WTh[4 * WOFF];         // transposed weights hi: 0:Dt 1:W1 2:W2 3:KG
__device__ __nv_bfloat16 g_WTl[4 * WOFF];

// ---------------- helpers ----------------
__device__ __forceinline__ uint32_t smem_to_u32(const void* p) {
    uint32_t a;
    asm("{ .reg .u64 t; cvta.to.shared.u64 t, %1; cvt.u32.u64 %0, t; }" : "=r"(a) : "l"(p));
    return a;
}
__device__ __forceinline__ float warp_sum(float v) {
#pragma unroll
    for (int o = 16; o > 0; o >>= 1) v += __shfl_xor_sync(0xffffffffu, v, o);
    return v;
}
__device__ __forceinline__ unsigned long long bcast2(float x) {
    unsigned long long r;
    asm("mov.b64 %0, {%1, %1};" : "=l"(r) : "f"(x));
    return r;
}
__device__ __forceinline__ float2 unpack2(unsigned long long v) {
    float2 f;
    asm("mov.b64 {%0, %1}, %2;" : "=f"(f.x), "=f"(f.y) : "l"(v));
    return f;
}
__device__ __forceinline__ void ffma2(unsigned long long& d, unsigned long long a, unsigned long long b) {
    asm("fma.rn.f32x2 %0, %1, %2, %0;" : "+l"(d) : "l"(a), "l"(b));
}
__device__ __forceinline__ void red_add_v4(float* p, float a, float b, float c, float d) {
    asm volatile("red.global.add.v4.f32 [%0], {%1, %2, %3, %4};"
                 :: "l"(p), "f"(a), "f"(b), "f"(c), "f"(d) : "memory");
}
__device__ __forceinline__ void cp16(uint32_t dst, const void* src, int src_bytes) {
    asm volatile("cp.async.cg.shared.global [%0], [%1], 16, %2;"
                 :: "r"(dst), "l"(src), "r"(src_bytes) : "memory");
}
#define CP_COMMIT() asm volatile("cp.async.commit_group;" ::: "memory")
template <int N>
__device__ __forceinline__ void cp_wait() {
    asm volatile("cp.async.wait_group %0;" :: "n"(N) : "memory");
}
__device__ __forceinline__ void ldsm4(uint32_t* r, uint32_t addr) {
    asm volatile("ldmatrix.sync.aligned.m8n8.x4.shared.b16 {%0,%1,%2,%3}, [%4];"
                 : "=r"(r[0]), "=r"(r[1]), "=r"(r[2]), "=r"(r[3]) : "r"(addr));
}
__device__ __forceinline__ void mma16816(float* d, const uint32_t* a, uint32_t b0, uint32_t b1) {
    asm volatile("mma.sync.aligned.m16n8k16.row.col.f32.bf16.bf16.f32 "
                 "{%0,%1,%2,%3}, {%4,%5,%6,%7}, {%8,%9}, {%0,%1,%2,%3};"
                 : "+f"(d[0]), "+f"(d[1]), "+f"(d[2]), "+f"(d[3])
                 : "r"(a[0]), "r"(a[1]), "r"(a[2]), "r"(a[3]), "r"(b0), "r"(b1));
}
__device__ __forceinline__ void split2(float v, __nv_bfloat16& h, __nv_bfloat16& l) {
    h = __float2bfloat16_rn(v);
    l = __float2bfloat16_rn(v - __bfloat162float(h));
}

// ---------------- small kernels ----------------
__global__ void zero_out_kernel(float* out) { if (threadIdx.x == 0 && blockIdx.x == 0) out[0] = 0.0f; }

__global__ void zero4_kernel(float4* p, int n4) {
    int i = blockIdx.x * blockDim.x + threadIdx.x;
    if (i < n4) p[i] = make_float4(0.f, 0.f, 0.f, 0.f);
}

__global__ void pad_weights_kernel(const float* __restrict__ Dense) {
    int idx = blockIdx.x * blockDim.x + threadIdx.x;
    if (idx >= 2 * SD * SD) return;
    int w = idx / (SD * SD);
    int rem = idx % (SD * SD);
    int r = rem / SD, c = rem % SD;
    float v = 0.f;
    if (r < D_N && c < D_N) v = Dense[(size_t)(D_N * (1 + w) + r) * D_N + c];
    g_Wt[idx] = v;
}

__global__ void wsplit_kernel(const float* __restrict__ Dense, const float* __restrict__ W1,
                              const float* __restrict__ W2, const float* __restrict__ KG) {
    int idx = blockIdx.x * blockDim.x + threadIdx.x;
    if (idx >= 4 * WOFF) return;
    int w = idx / WOFF;
    int rem = idx % WOFF;
    int n = rem / 320, k = rem % 320;
    float v = 0.f;
    if (n < D_N && k < D_N) {
        const float* src = (w == 0) ? Dense : (w == 1) ? W1 : (w == 2) ? W2 : KG;
        v = src[(size_t)k * D_N + n];
    }
    __nv_bfloat16 hi, lo;
    split2(v, hi, lo);
    g_WTh[idx] = hi;
    g_WTl[idx] = lo;
}

// normalize + emb splits (to Bh/Bl). Warp per row.
__global__ void normalize_kernel(const float* __restrict__ we) {
    int warp = (blockIdx.x * blockDim.x + threadIdx.x) >> 5;
    int lane = threadIdx.x & 31;
    if (warp >= E_N) return;
    const float4* src = (const float4*)(we + (size_t)warp * D_N);
    float4 v[3];
    float s = 0.f;
#pragma unroll
    for (int it = 0; it < 3; it++) {
        int j = lane + it * 32;
        if (j < D4) {
            float4 x = src[j];
            v[it] = x;
            s += x.x * x.x + x.y * x.y + x.z * x.z + x.w * x.w;
        } else v[it] = make_float4(0.f, 0.f, 0.f, 0.f);
    }
    s = warp_sum(s);
    float inv = 1.0f / sqrtf(s);
    float4* dst = (float4*)(g_emb + (size_t)warp * SD);
    __nv_bfloat162* bh = (__nv_bfloat162*)(g_Bh + (size_t)warp * SD);
    __nv_bfloat162* bl = (__nv_bfloat162*)(g_Bl + (size_t)warp * SD);
#pragma unroll
    for (int it = 0; it < 3; it++) {
        int j = lane + it * 32;
        if (j < SD4) {
            float4 o = make_float4(0.f, 0.f, 0.f, 0.f);
            if (j < D4) o = make_float4(v[it].x * inv, v[it].y * inv, v[it].z * inv, v[it].w * inv);
            dst[j] = o;
            float xs[4] = {o.x, o.y, o.z, o.w};
            __nv_bfloat16 h[4], l[4];
#pragma unroll
            for (int q = 0; q < 4; q++) split2(xs[q], h[q], l[q]);
            __nv_bfloat162 h0, h1, l0, l1;
            h0.x = h[0]; h0.y = h[1]; h1.x = h[2]; h1.y = h[3];
            l0.x = l[0]; l0.y = l[1]; l1.x = l[2]; l1.y = l[3];
            bh[2 * j] = h0; bh[2 * j + 1] = h1;
            bl[2 * j] = l0; bl[2 * j + 1] = l1;
        }
    }
}

// COO SpMM scatter with vector reductions. Warp per nnz.
__global__ void spmm_kernel(const int* __restrict__ rows, const int* __restrict__ cols,
                            const float* __restrict__ vals, int nnz,
                            const float* __restrict__ X, float* __restrict__ Out,
                            int rel_mode) {
    int warp = (blockIdx.x * blockDim.x + threadIdx.x) >> 5;
    int lane = threadIdx.x & 31;
    if (warp >= nnz) return;
    int   r = rows[warp];
    int   c = cols[warp];
    float v = vals[warp];
    if (rel_mode && c >= R_N) { c -= R_N; v = -v; }
    const float4* xr = (const float4*)(X + (size_t)c * SD);
    float* orow = Out + (size_t)r * SD;
#pragma unroll
    for (int it = 0; it < 3; it++) {
        int j = lane + it * 32;
        if (j < D4) {
            float4 x = xr[j];
            red_add_v4(orow + j * 4, v * x.x, v * x.y, v * x.z, v * x.w);
        }
    }
}

// ---------------- HMMA GEMM (bf16 split-2): C[M,320] = X @ W ----------------
// Block 128m x 64n, 8 warps as 4m x 2n groups, warp tile 32x32. K-chunk 32,
// double buffered, 3 CTAs/SM.
// mode 0: store fp32 (+ optional zero-fill of Z at same addresses)
// mode 3: highway epilogue; mode 4: highway + write bf16 splits to Oh/Ol.
#define MMK 32
#define MMS 40                         // smem row stride bf16 (32 + 8 pad)
#define A_TB (128 * MMS * 2)           // 10240 B
#define B_TB (64 * MMS * 2)            // 5120 B
#define MM_STAGE (2 * A_TB + 2 * B_TB) // 30720 B
#define MM_SMEM  (2 * MM_STAGE)        // 61440 B
#define MM_CH 10                       // 320 / 32

__device__ __forceinline__ void mm_load_stage(uint32_t sb,
                                              const __nv_bfloat16* Xh, const __nv_bfloat16* Xl,
                                              const __nv_bfloat16* Wh, const __nv_bfloat16* Wl,
                                              int bm, int bn, int M, int k0, int tid) {
#pragma unroll
    for (int q = 0; q < 6; q++) {
        int idx = q * 256 + tid;
        if (idx < 1024) {
            int part = idx >> 9;               // 0: Ah, 1: Al
            int r = (idx & 511) >> 2, c = idx & 3;
            const __nv_bfloat16* src = (part ? Xl : Xh) + (size_t)(bm + r) * 320 + k0 + c * 8;
            int ok = (bm + r < M) ? 16 : 0;
            cp16(sb + part * A_TB + r * (MMS * 2) + c * 16, src, ok);
        } else {
            int t = idx - 1024;
            int part = t >> 8;                 // 0: Bh, 1: Bl
            int rr = t & 255;
            int r = rr >> 2, c = rr & 3;
            const __nv_bfloat16* src = (part ? Wl : Wh) + (size_t)(bn + r) * 320 + k0 + c * 8;
            cp16(sb + 2 * A_TB + part * B_TB + r * (MMS * 2) + c * 16, src, 16);
        }
    }
    CP_COMMIT();
}

__global__ __launch_bounds__(256, 3) void mgemm_kernel(const __nv_bfloat16* __restrict__ Xh,
                                                       const __nv_bfloat16* __restrict__ Xl,
                                                       const __nv_bfloat16* __restrict__ Wh,
                                                       const __nv_bfloat16* __restrict__ Wl,
                                                       float* __restrict__ C, int M, int mode,
                                                       const float* __restrict__ ep1,
                                                       const float* __restrict__ ep2,
                                                       const float* __restrict__ epv,
                                                       __nv_bfloat16* __restrict__ Oh,
                                                       __nv_bfloat16* __restrict__ Ol,
                                                       float* __restrict__ Z) {
    extern __shared__ char sm8[];
    uint32_t smb = smem_to_u32(sm8);
    int tid = threadIdx.x, wid = tid >> 5, lane = tid & 31;
    int bn = blockIdx.x * 64, bm = blockIdx.y * 128;
    int wm = (wid >> 1) * 32;      // 4 m-groups of 32
    int wn = (wid & 1) * 32;       // 2 n-groups of 32

    float acc[2][4][4];
#pragma unroll
    for (int i = 0; i < 2; i++)
#pragma unroll
        for (int j = 0; j < 4; j++)
#pragma unroll
            for (int q = 0; q < 4; q++) acc[i][j][q] = 0.f;

    int aRow = lane & 15, aKsel = (lane >> 4) * 8;
    int bRow = (lane >> 4) * 8 + (lane & 7), bKsel = ((lane >> 3) & 1) * 8;

    mm_load_stage(smb, Xh, Xl, Wh, Wl, bm, bn, M, 0, tid);

    for (int ch = 0; ch < MM_CH; ch++) {
        uint32_t sb = smb + (ch & 1) * MM_STAGE;
        if (ch + 1 < MM_CH)
            mm_load_stage(smb + ((ch + 1) & 1) * MM_STAGE, Xh, Xl, Wh, Wl, bm, bn, M, (ch + 1) * MMK, tid);
        if (ch + 1 < MM_CH) cp_wait<1>(); else cp_wait<0>();
        __syncthreads();
#pragma unroll
        for (int ks = 0; ks < 2; ks++) {
            int k0 = ks * 16;
            uint32_t ah[2][4], al[2][4], bh[2][4], bl[2][4];
#pragma unroll
            for (int i = 0; i < 2; i++) {
                uint32_t ad = sb + ((wm + i * 16 + aRow) * MMS + k0 + aKsel) * 2;
                ldsm4(ah[i], ad);
                ldsm4(al[i], ad + A_TB);
            }
#pragma unroll
            for (int j = 0; j < 2; j++) {
                uint32_t bd = sb + 2 * A_TB + ((wn + j * 16 + bRow) * MMS + k0 + bKsel) * 2;
                ldsm4(bh[j], bd);
                ldsm4(bl[j], bd + B_TB);
            }
#pragma unroll
            for (int i = 0; i < 2; i++)
#pragma unroll
                for (int j = 0; j < 2; j++)
#pragma unroll
                    for (int t = 0; t < 2; t++) {
                        float* a4 = acc[i][j * 2 + t];
                        mma16816(a4, ah[i], bh[j][t * 2], bh[j][t * 2 + 1]);
                        mma16816(a4, ah[i], bl[j][t * 2], bl[j][t * 2 + 1]);
                        mma16816(a4, al[i], bh[j][t * 2], bh[j][t * 2 + 1]);
                    }
        }
        __syncthreads();
    }

    // epilogue: warp covers rows [bm+wm, +32), cols [bn+wn, +32)
#pragma unroll
    for (int i = 0; i < 2; i++)
#pragma unroll
        for (int jj = 0; jj < 4; jj++) {
            int col = bn + wn + jj * 8 + (lane & 3) * 2;
#pragma unroll
            for (int half = 0; half < 2; half++) {
                int row = bm + wm + i * 16 + (lane >> 2) + half * 8;
                if (row >= M) continue;
                float v0 = acc[i][jj][half * 2], v1 = acc[i][jj][half * 2 + 1];
                float* crow = C + (size_t)row * SD + col;
                if (mode == 0) {
                    *(float2*)crow = make_float2(v0, v1);
                    if (Z) *(float2*)(Z + (size_t)row * SD + col) = make_float2(0.f, 0.f);
                } else {
                    const float* l1 = ep1 + (size_t)row * SD + col;
                    const float* gc = ep2 + (size_t)row * SD + col;
                    float2 a = *(const float2*)l1;
                    float2 g = *(const float2*)gc;
                    float o0 = 0.f, o1 = 0.f;
                    if (col < D_N) {
                        float tg = 1.0f / (1.0f + expf(-(v0 + epv[col])));
                        o0 = tg * fmaxf(g.x, 0.f) + (1.0f - tg) * a.x;
                    }
                    if (col + 1 < D_N) {
                        float tg = 1.0f / (1.0f + expf(-(v1 + epv[col + 1])));
                        o1 = tg * fmaxf(g.y, 0.f) + (1.0f - tg) * a.y;
                    }
                    *(float2*)crow = make_float2(o0, o1);
                    if (mode == 4) {
                        __nv_bfloat16 h0, h1, l0, l1b;
                        split2(o0, h0, l0);
                        split2(o1, h1, l1b);
                        __nv_bfloat162 hh, ll;
                        hh.x = h0; hh.y = h1;
                        ll.x = l0; ll.y = l1b;
                        *(__nv_bfloat162*)(Oh + (size_t)row * SD + col) = hh;
                        *(__nv_bfloat162*)(Ol + (size_t)row * SD + col) = ll;
                    }
                }
            }
        }
}

// ---------------- FFMA2 SGEMM (small R_N GEMMs) ----------------
#define BM 256
#define BN 64
#define BK 16
#define KTILES 19
__global__ __launch_bounds__(256, 2) void sgemm_kernel(const float* __restrict__ A,
                                                       const float* __restrict__ B,
                                                       float* __restrict__ C,
                                                       int M, int accumulate) {
    __shared__ float As[2][BK][BM];
    __shared__ float Bs[2][BK][BN];
    int bm = blockIdx.y * BM;
    int bn = blockIdx.x * BN;
    int tid = threadIdx.x;
    int tx = tid & 7;
    int ty = tid >> 3;
    int arow = bm + tid;
    bool avalid = arow < M;
    const float* Aptr = A + (size_t)arow * SD;
    int brow  = tid >> 4;
    int bcol4 = tid & 15;
    const float* Bptr = B + (size_t)brow * SD + bn + bcol4 * 4;

    unsigned long long acc[8][4];
#pragma unroll
    for (int i = 0; i < 8; i++)
#pragma unroll
        for (int j = 0; j < 4; j++) acc[i][j] = 0ull;

    float4 ra[4], rb;
#pragma unroll
    for (int c = 0; c < 4; c++)
        ra[c] = avalid ? *(const float4*)(Aptr + c * 4) : make_float4(0.f, 0.f, 0.f, 0.f);
    rb = *(const float4*)(Bptr);
#pragma unroll
    for (int c = 0; c < 4; c++) {
        As[0][c * 4 + 0][tid] = ra[c].x;
        As[0][c * 4 + 1][tid] = ra[c].y;
        As[0][c * 4 + 2][tid] = ra[c].z;
        As[0][c * 4 + 3][tid] = ra[c].w;
    }
    *(float4*)(&Bs[0][brow][bcol4 * 4]) = rb;
    __syncthreads();

    for (int t = 0; t < KTILES; t++) {
        int cur = t & 1, nxt = cur ^ 1;
        if (t + 1 < KTILES) {
            int k0 = (t + 1) * BK;
#pragma unroll
            for (int c = 0; c < 4; c++)
                ra[c] = avalid ? *(const float4*)(Aptr + k0 + c * 4) : make_float4(0.f, 0.f, 0.f, 0.f);
            rb = *(const float4*)(Bptr + (size_t)k0 * SD);
        }
#pragma unroll
        for (int k = 0; k < BK; k++) {
            ulonglong2 bb0 = *(const ulonglong2*)(&Bs[cur][k][tx * 8]);
            ulonglong2 bb1 = *(const ulonglong2*)(&Bs[cur][k][tx * 8 + 4]);
            unsigned long long b2[4] = {bb0.x, bb0.y, bb1.x, bb1.y};
            float4 a0 = *(const float4*)(&As[cur][k][ty * 8]);
            float4 a1 = *(const float4*)(&As[cur][k][ty * 8 + 4]);
            unsigned long long a2[8];
            a2[0] = bcast2(a0.x); a2[1] = bcast2(a0.y); a2[2] = bcast2(a0.z); a2[3] = bcast2(a0.w);
            a2[4] = bcast2(a1.x); a2[5] = bcast2(a1.y); a2[6] = bcast2(a1.z); a2[7] = bcast2(a1.w);
#pragma unroll
            for (int i = 0; i < 8; i++)
#pragma unroll
                for (int j = 0; j < 4; j++)
                    ffma2(acc[i][j], a2[i], b2[j]);
        }
        if (t + 1 < KTILES) {
#pragma unroll
            for (int c = 0; c < 4; c++) {
                As[nxt][c * 4 + 0][tid] = ra[c].x;
                As[nxt][c * 4 + 1][tid] = ra[c].y;
                As[nxt][c * 4 + 2][tid] = ra[c].z;
                As[nxt][c * 4 + 3][tid] = ra[c].w;
            }
            *(float4*)(&Bs[nxt][brow][bcol4 * 4]) = rb;
        }
        __syncthreads();
    }

    int gcol = bn + tx * 8;
#pragma unroll
    for (int i = 0; i < 8; i++) {
        int grow = bm + ty * 8 + i;
        if (grow >= M) continue;
        float2 u0 = unpack2(acc[i][0]);
        float2 u1 = unpack2(acc[i][1]);
        float2 u2 = unpack2(acc[i][2]);
        float2 u3 = unpack2(acc[i][3]);
        float* crow = C + (size_t)grow * SD + gcol;
        if (accumulate) {
            float4 c0 = *(float4*)crow;
            float4 c1 = *(float4*)(crow + 4);
            *(float4*)crow       = make_float4(c0.x + u0.x, c0.y + u0.y, c0.z + u1.x, c0.w + u1.y);
            *(float4*)(crow + 4) = make_float4(c1.x + u2.x, c1.y + u2.y, c1.z + u3.x, c1.w + u3.y);
        } else {
            *(float4*)crow       = make_float4(u0.x, u0.y, u1.x, u1.y);
            *(float4*)(crow + 4) = make_float4(u2.x, u2.y, u3.x, u3.y);
        }
    }
}

// h = emb + relu(h_pre + Bias); pads -> 0; also writes h splits to Ch/Cl.
__global__ void h_kernel(const float* __restrict__ Bias) {
    int i = blockIdx.x * blockDim.x + threadIdx.x;   // float4 index
    if (i >= E_N * SD4) return;
    int j = i % SD4;
    float4 o = make_float4(0.f, 0.f, 0.f, 0.f);
    if (j < D4) {
        float4 p = ((const float4*)g_A1)[i];
        float4 e = ((const float4*)g_emb)[i];
        int d = j * 4;
        o.x = e.x + fmaxf(p.x + Bias[d + 0], 0.f);
        o.y = e.y + fmaxf(p.y + Bias[d + 1], 0.f);
        o.z = e.z + fmaxf(p.z + Bias[d + 2], 0.f);
        o.w = e.w + fmaxf(p.w + Bias[d + 3], 0.f);
    }
    ((float4*)g_A2)[i] = o;
    float xs[4] = {o.x, o.y, o.z, o.w};
    __nv_bfloat16 h[4], l[4];
#pragma unroll
    for (int q = 0; q < 4; q++) split2(xs[q], h[q], l[q]);
    __nv_bfloat162 h0, h1, l0, l1;
    h0.x = h[0]; h0.y = h[1]; h1.x = h[2]; h1.y = h[3];
    l0.x = l[0]; l0.y = l[1]; l1.x = l[2]; l1.y = l[3];
    ((__nv_bfloat162*)g_Ch)[2 * i]     = h0;
    ((__nv_bfloat162*)g_Ch)[2 * i + 1] = h1;
    ((__nv_bfloat162*)g_Cl)[2 * i]     = l0;
    ((__nv_bfloat162*)g_Cl)[2 * i + 1] = l1;
}

// Fused hinge loss: one block per pair t.
__global__ __launch_bounds__(256) void loss_kernel(const int* __restrict__ pl,
                                                   const int* __restrict__ pr,
                                                   const int* __restrict__ nr,
                                                   const int* __restrict__ nl,
                                                   const float* __restrict__ mask,
                                                   const float* __restrict__ node,
                                                   float* __restrict__ out) {
    __shared__ float4 sl[D4], sr[D4];
    __shared__ float wpart[8];
    __shared__ float s_dm;
    int t    = blockIdx.x;
    int tid  = threadIdx.x;
    int lane = tid & 31;
    int wid  = tid >> 5;

    const float4* xl = (const float4*)(node + (size_t)pl[t] * SD);
    const float4* xr = (const float4*)(node + (size_t)pr[t] * SD);
    float d = 0.f;
    if (tid < D4) {
        float4 a = xl[tid], b = xr[tid];
        sl[tid] = a; sr[tid] = b;
        d = fabsf(a.x - b.x) + fabsf(a.y - b.y) + fabsf(a.z - b.z) + fabsf(a.w - b.w);
    }
    d = warp_sum(d);
    if (lane == 0) wpart[wid] = d;
    __syncthreads();
    if (tid == 0) s_dm = wpart[0] + wpart[1] + wpart[2] + GAMMA_F;
    __syncthreads();
    float dm = s_dm;

    float hsum = 0.f;
    for (int k = wid; k < K_N; k += 8) {
        int i = t * K_N + k;
        const float4* xR = (const float4*)(node + (size_t)nr[i] * SD);
        const float4* xL = (const float4*)(node + (size_t)nl[i] * SD);
        float s1 = 0.f, s2 = 0.f;
#pragma unroll
        for (int it = 0; it < 3; it++) {
            int j = lane + it * 32;
            if (j < D4) {
                float4 a = sl[j], b = sr[j], cr = xR[j], cl = xL[j];
                s1 += fabsf(a.x - cr.x) + fabsf(a.y - cr.y) + fabsf(a.z - cr.z) + fabsf(a.w - cr.w);
                s2 += fabsf(cl.x - b.x) + fabsf(cl.y - b.y) + fabsf(cl.z - b.z) + fabsf(cl.w - b.w);
            }
        }
        s1 = warp_sum(s1);
        s2 = warp_sum(s2);
        if (lane == 0) hsum += (fmaxf(dm - s1, 0.f) + fmaxf(dm - s2, 0.f)) * mask[i];
    }
    if (lane == 0) wpart[wid] = hsum;
    __syncthreads();
    if (tid == 0) {
        float tot = 0.f;
#pragma unroll
        for (int w = 0; w < 8; w++) tot += wpart[w];
        atomicAdd(out, tot * 0.5f);
    }
}

// ---------------- host ----------------
extern "C" void kernel_launch(void* const* d_in, const int* in_sizes, int n_in,
                              void* d_out, int out_size) {
    const float* we    = (const float*)d_in[0];
    const float* kgw   = (const float*)d_in[1];
    const float* bg    = (const float*)d_in[2];
    const float* W1    = (const float*)d_in[3];
    const float* W2    = (const float*)d_in[4];
    const float* Dense = (const float*)d_in[5];
    const float* Bias  = (const float*)d_in[6];
    const int*   hr_rows = (const int*)d_in[7];
    const int*   hr_cols = (const int*)d_in[8];
    const float* hr_vals = (const float*)d_in[9];
    const int*   tr_rows = (const int*)d_in[10];
    const int*   tr_cols = (const int*)d_in[11];
    const float* tr_vals = (const float*)d_in[12];
    const int*   er_rows = (const int*)d_in[13];
    const int*   er_cols = (const int*)d_in[14];
    const float* er_vals = (const float*)d_in[15];
    const int*   adj_rows = (const int*)d_in[16];
    const int*   adj_cols = (const int*)d_in[17];
    const float* adj_vals = (const float*)d_in[18];
    const int*   pos_left  = (const int*)d_in[19];
    const int*   pos_right = (const int*)d_in[20];
    const int*   neg_right = (const int*)d_in[21];
    const int*   neg_left  = (const int*)d_in[22];
    const float* mask      = (const float*)d_in[23];
    float* out = (float*)d_out;

    int nnz_hr  = in_sizes[7];
    int nnz_tr  = in_sizes[10];
    int nnz_er  = in_sizes[13];
    int nnz_adj = in_sizes[16];

    float *p_emb, *p_A1, *p_A2, *p_A3, *p_A5, *p_A6, *p_Lm, *p_Rm, *p_P, *p_Wt;
    __nv_bfloat16 *p_Bh, *p_Bl, *p_Ch, *p_Cl, *p_WTh, *p_WTl;
    cudaGetSymbolAddress((void**)&p_emb, g_emb);
    cudaGetSymbolAddress((void**)&p_A1,  g_A1);
    cudaGetSymbolAddress((void**)&p_A2,  g_A2);
    cudaGetSymbolAddress((void**)&p_A3,  g_A3);
    cudaGetSymbolAddress((void**)&p_A5,  g_A5);
    cudaGetSymbolAddress((void**)&p_A6,  g_A6);
    cudaGetSymbolAddress((void**)&p_Lm,  g_Lm);
    cudaGetSymbolAddress((void**)&p_Rm,  g_Rm);
    cudaGetSymbolAddress((void**)&p_P,   g_P);
    cudaGetSymbolAddress((void**)&p_Wt,  g_Wt);
    cudaGetSymbolAddress((void**)&p_Bh,  g_Bh);
    cudaGetSymbolAddress((void**)&p_Bl,  g_Bl);
    cudaGetSymbolAddress((void**)&p_Ch,  g_Ch);
    cudaGetSymbolAddress((void**)&p_Cl,  g_Cl);
    cudaGetSymbolAddress((void**)&p_WTh, g_WTh);
    cudaGetSymbolAddress((void**)&p_WTl, g_WTl);

    cudaFuncSetAttribute(mgemm_kernel, cudaFuncAttributeMaxDynamicSharedMemorySize, MM_SMEM);

    dim3 mmGrid(5, (E_N + 127) / 128);
    dim3 gemmGridR(SD / BN, (R_N + BM - 1) / BM);

    // 1-3, then launch #4 = first HMMA GEMM (profiled)
    wsplit_kernel<<<(4 * WOFF + 255) / 256, 256>>>(Dense, W1, W2, kgw);
    normalize_kernel<<<(E_N * 32) / 256, 256>>>(we);
    zero4_kernel<<<(R_N * SD / 4 + 255) / 256, 256>>>((float4*)p_Lm, R_N * SD / 4);
    mgemm_kernel<<<mmGrid, 256, MM_SMEM>>>(p_Bh, p_Bl, p_WTh, p_WTl, p_A1, E_N, 0, 0, 0, 0, 0, 0, 0);

    // relation aggregation
    zero4_kernel<<<(R_N * SD / 4 + 255) / 256, 256>>>((float4*)p_Rm, R_N * SD / 4);
    spmm_kernel<<<(nnz_hr + 7) / 8, 256>>>(hr_rows, hr_cols, hr_vals, nnz_hr, p_emb, p_Lm, 0);
    spmm_kernel<<<(nnz_tr + 7) / 8, 256>>>(tr_rows, tr_cols, tr_vals, nnz_tr, p_emb, p_Rm, 0);

    // P = L @ Db1 + Rm @ Db2
    pad_weights_kernel<<<(2 * SD * SD + 255) / 256, 256>>>(Dense);
    sgemm_kernel<<<gemmGridR, 256>>>(p_Lm, p_Wt, p_P, R_N, 0);
    sgemm_kernel<<<gemmGridR, 256>>>(p_Rm, p_Wt + SD * SD, p_P, R_N, 1);

    // h_pre += spmm(er, +-P)
    spmm_kernel<<<(nnz_er + 7) / 8, 256>>>(er_rows, er_cols, er_vals, nnz_er, p_P, p_A1, 1);

    zero_out_kernel<<<1, 1>>>(out);

    // h = emb + relu(h_pre + Bias)  (+ h splits -> Ch/Cl)
    h_kernel<<<(E_N * SD4 + 255) / 256, 256>>>(Bias);

    // layer 1: t1 = h@W1 -> A3 (also zeroes A5); gcn1 -> A5; gate GEMM fuses highway -> A6 (+ splits -> Bh/Bl)
    mgemm_kernel<<<mmGrid, 256, MM_SMEM>>>(p_Ch, p_Cl, p_WTh + 1 * WOFF, p_WTl + 1 * WOFF, p_A3, E_N, 0, 0, 0, 0, 0, 0, p_A5);
    spmm_kernel<<<(nnz_adj + 7) / 8, 256>>>(adj_rows, adj_cols, adj_vals, nnz_adj, p_A3, p_A5, 0);
    mgemm_kernel<<<mmGrid, 256, MM_SMEM>>>(p_Ch, p_Cl, p_WTh + 3 * WOFF, p_WTl + 3 * WOFF, p_A6, E_N, 4, p_A2, p_A5, bg, p_Bh, p_Bl, 0);

    // layer 2: t2 = hg1@W2 -> A3 (also zeroes A1); gcn2 -> A1; gate GEMM fuses highway -> node (A2)
    mgemm_kernel<<<mmGrid, 256, MM_SMEM>>>(p_Bh, p_Bl, p_WTh + 2 * WOFF, p_WTl + 2 * WOFF, p_A3, E_N, 0, 0, 0, 0, 0, 0, p_A1);
    spmm_kernel<<<(nnz_adj + 7) / 8, 256>>>(adj_rows, adj_cols, adj_vals, nnz_adj, p_A3, p_A1, 0);
    mgemm_kernel<<<mmGrid, 256, MM_SMEM>>>(p_Bh, p_Bl, p_WTh + 3 * WOFF, p_WTl + 3 * WOFF, p_A2, E_N, 3, p_A6, p_A1, bg, 0, 0, 0);

    // fused loss
    loss_kernel<<<T_N, 256>>>(pos_left, pos_right, neg_right, neg_left, mask, p_A2, out);
    (void)n_in; (void)out_size;
}

// round 13
// speedup vs baseline: 1.7977x; 1.0016x over previous
#include <cuda_runtime.h>
#include <cuda_bf16.h>
#include <math.h>
#include <stdint.h>

#define E_N 100000
#define D_N 300
#define R_N 1000
#define T_N 10000
#define K_N 25
#define SD  320
#define D4  75
#define SD4 80
#define GAMMA_F 1.0f
#define WOFF (320*320)

// ---------------- scratch (device globals: allocation-free) ----------------
__device__ float g_emb[(size_t)E_N * SD];
__device__ float g_A1 [(size_t)E_N * SD];
__device__ float g_A2 [(size_t)E_N * SD];
__device__ float g_A3 [(size_t)E_N * SD];
__device__ float g_A5 [(size_t)E_N * SD];
__device__ float g_A6 [(size_t)E_N * SD];
__device__ float g_Lm [R_N * SD];
__device__ float g_Rm [R_N * SD];
__device__ float g_P  [R_N * SD];
__device__ float g_Wt [2 * SD * SD];
__device__ __nv_bfloat16 g_Bh[(size_t)E_N * SD];  // split pair A (emb, then hg1)
__device__ __nv_bfloat16 g_Bl[(size_t)E_N * SD];
__device__ __nv_bfloat16 g_Ch[(size_t)E_N * SD];  // split pair B (h)
__device__ __nv_bfloat16 g_Cl[(size_t)E_N * SD];
__device__ __nv_bfloat16 g_WTh[4 * WOFF];         // transposed weights hi: 0:Dt 1:W1 2:W2 3:KG
__device__ __nv_bfloat16 g_WTl[4 * WOFF];

// ---------------- helpers ----------------
__device__ __forceinline__ uint32_t smem_to_u32(const void* p) {
    uint32_t a;
    asm("{ .reg .u64 t; cvta.to.shared.u64 t, %1; cvt.u32.u64 %0, t; }" : "=r"(a) : "l"(p));
    return a;
}
__device__ __forceinline__ float warp_sum(float v) {
#pragma unroll
    for (int o = 16; o > 0; o >>= 1) v += __shfl_xor_sync(0xffffffffu, v, o);
    return v;
}
__device__ __forceinline__ unsigned long long bcast2(float x) {
    unsigned long long r;
    asm("mov.b64 %0, {%1, %1};" : "=l"(r) : "f"(x));
    return r;
}
__device__ __forceinline__ float2 unpack2(unsigned long long v) {
    float2 f;
    asm("mov.b64 {%0, %1}, %2;" : "=f"(f.x), "=f"(f.y) : "l"(v));
    return f;
}
__device__ __forceinline__ void ffma2(unsigned long long& d, unsigned long long a, unsigned long long b) {
    asm("fma.rn.f32x2 %0, %1, %2, %0;" : "+l"(d) : "l"(a), "l"(b));
}
__device__ __forceinline__ void red_add_v4(float* p, float a, float b, float c, float d) {
    asm volatile("red.global.add.v4.f32 [%0], {%1, %2, %3, %4};"
                 :: "l"(p), "f"(a), "f"(b), "f"(c), "f"(d) : "memory");
}
__device__ __forceinline__ void cp16(uint32_t dst, const void* src, int src_bytes) {
    asm volatile("cp.async.cg.shared.global [%0], [%1], 16, %2;"
                 :: "r"(dst), "l"(src), "r"(src_bytes) : "memory");
}
#define CP_COMMIT() asm volatile("cp.async.commit_group;" ::: "memory")
template <int N>
__device__ __forceinline__ void cp_wait() {
    asm volatile("cp.async.wait_group %0;" :: "n"(N) : "memory");
}
__device__ __forceinline__ void ldsm4(uint32_t* r, uint32_t addr) {
    asm volatile("ldmatrix.sync.aligned.m8n8.x4.shared.b16 {%0,%1,%2,%3}, [%4];"
                 : "=r"(r[0]), "=r"(r[1]), "=r"(r[2]), "=r"(r[3]) : "r"(addr));
}
__device__ __forceinline__ void mma16816(float* d, const uint32_t* a, uint32_t b0, uint32_t b1) {
    asm volatile("mma.sync.aligned.m16n8k16.row.col.f32.bf16.bf16.f32 "
                 "{%0,%1,%2,%3}, {%4,%5,%6,%7}, {%8,%9}, {%0,%1,%2,%3};"
                 : "+f"(d[0]), "+f"(d[1]), "+f"(d[2]), "+f"(d[3])
                 : "r"(a[0]), "r"(a[1]), "r"(a[2]), "r"(a[3]), "r"(b0), "r"(b1));
}
__device__ __forceinline__ void split2(float v, __nv_bfloat16& h, __nv_bfloat16& l) {
    h = __float2bfloat16_rn(v);
    l = __float2bfloat16_rn(v - __bfloat162float(h));
}

// ---------------- small kernels ----------------
__global__ void zero_out_kernel(float* out) { if (threadIdx.x == 0 && blockIdx.x == 0) out[0] = 0.0f; }

__global__ void zero4_kernel(float4* p, int n4) {
    int i = blockIdx.x * blockDim.x + threadIdx.x;
    if (i < n4) p[i] = make_float4(0.f, 0.f, 0.f, 0.f);
}

__global__ void pad_weights_kernel(const float* __restrict__ Dense) {
    int idx = blockIdx.x * blockDim.x + threadIdx.x;
    if (idx >= 2 * SD * SD) return;
    int w = idx / (SD * SD);
    int rem = idx % (SD * SD);
    int r = rem / SD, c = rem % SD;
    float v = 0.f;
    if (r < D_N && c < D_N) v = Dense[(size_t)(D_N * (1 + w) + r) * D_N + c];
    g_Wt[idx] = v;
}

__global__ void wsplit_kernel(const float* __restrict__ Dense, const float* __restrict__ W1,
                              const float* __restrict__ W2, const float* __restrict__ KG) {
    int idx = blockIdx.x * blockDim.x + threadIdx.x;
    if (idx >= 4 * WOFF) return;
    int w = idx / WOFF;
    int rem = idx % WOFF;
    int n = rem / 320, k = rem % 320;
    float v = 0.f;
    if (n < D_N && k < D_N) {
        const float* src = (w == 0) ? Dense : (w == 1) ? W1 : (w == 2) ? W2 : KG;
        v = src[(size_t)k * D_N + n];
    }
    __nv_bfloat16 hi, lo;
    split2(v, hi, lo);
    g_WTh[idx] = hi;
    g_WTl[idx] = lo;
}

// normalize + emb splits (to Bh/Bl). Warp per row.
__global__ void normalize_kernel(const float* __restrict__ we) {
    int warp = (blockIdx.x * blockDim.x + threadIdx.x) >> 5;
    int lane = threadIdx.x & 31;
    if (warp >= E_N) return;
    const float4* src = (const float4*)(we + (size_t)warp * D_N);
    float4 v[3];
    float s = 0.f;
#pragma unroll
    for (int it = 0; it < 3; it++) {
        int j = lane + it * 32;
        if (j < D4) {
            float4 x = src[j];
            v[it] = x;
            s += x.x * x.x + x.y * x.y + x.z * x.z + x.w * x.w;
        } else v[it] = make_float4(0.f, 0.f, 0.f, 0.f);
    }
    s = warp_sum(s);
    float inv = 1.0f / sqrtf(s);
    float4* dst = (float4*)(g_emb + (size_t)warp * SD);
    __nv_bfloat162* bh = (__nv_bfloat162*)(g_Bh + (size_t)warp * SD);
    __nv_bfloat162* bl = (__nv_bfloat162*)(g_Bl + (size_t)warp * SD);
#pragma unroll
    for (int it = 0; it < 3; it++) {
        int j = lane + it * 32;
        if (j < SD4) {
            float4 o = make_float4(0.f, 0.f, 0.f, 0.f);
            if (j < D4) o = make_float4(v[it].x * inv, v[it].y * inv, v[it].z * inv, v[it].w * inv);
            dst[j] = o;
            float xs[4] = {o.x, o.y, o.z, o.w};
            __nv_bfloat16 h[4], l[4];
#pragma unroll
            for (int q = 0; q < 4; q++) split2(xs[q], h[q], l[q]);
            __nv_bfloat162 h0, h1, l0, l1;
            h0.x = h[0]; h0.y = h[1]; h1.x = h[2]; h1.y = h[3];
            l0.x = l[0]; l0.y = l[1]; l1.x = l[2]; l1.y = l[3];
            bh[2 * j] = h0; bh[2 * j + 1] = h1;
            bl[2 * j] = l0; bl[2 * j + 1] = l1;
        }
    }
}

// COO SpMM scatter with vector reductions. Warp per nnz.
__global__ void spmm_kernel(const int* __restrict__ rows, const int* __restrict__ cols,
                            const float* __restrict__ vals, int nnz,
                            const float* __restrict__ X, float* __restrict__ Out,
                            int rel_mode) {
    int warp = (blockIdx.x * blockDim.x + threadIdx.x) >> 5;
    int lane = threadIdx.x & 31;
    if (warp >= nnz) return;
    int   r = rows[warp];
    int   c = cols[warp];
    float v = vals[warp];
    if (rel_mode && c >= R_N) { c -= R_N; v = -v; }
    const float4* xr = (const float4*)(X + (size_t)c * SD);
    float* orow = Out + (size_t)r * SD;
#pragma unroll
    for (int it = 0; it < 3; it++) {
        int j = lane + it * 32;
        if (j < D4) {
            float4 x = xr[j];
            red_add_v4(orow + j * 4, v * x.x, v * x.y, v * x.z, v * x.w);
        }
    }
}

// ---------------- HMMA GEMM (bf16 split-2): C[M,320] = X @ W ----------------
// Block 128m x 160n, 8 warps as 4m x 2n groups, warp tile 32x80. K-chunk 32,
// double buffered, 2 CTAs/SM.
// mode 0: store fp32 (+ optional zero-fill of Z)
// mode 3: highway epilogue; mode 4: highway + write bf16 splits to Oh/Ol.
#define MMN 160
#define MMK 32
#define MMS 40                         // smem row stride bf16 (32 + 8 pad)
#define A_TB (128 * MMS * 2)           // 10240 B
#define B_TB (MMN * MMS * 2)           // 12800 B
#define MM_STAGE (2 * A_TB + 2 * B_TB) // 46080 B
#define MM_SMEM  (2 * MM_STAGE)        // 92160 B
#define MM_CH 10                       // 320 / 32

__device__ __forceinline__ void mm_load_stage(uint32_t sb,
                                              const __nv_bfloat16* Xh, const __nv_bfloat16* Xl,
                                              const __nv_bfloat16* Wh, const __nv_bfloat16* Wl,
                                              int bm, int bn, int M, int k0, int tid) {
    // A: 2 parts x 128 rows x 4 16B-chunks = 1024 ; B: 2 parts x 160 rows x 4 = 1280
#pragma unroll
    for (int q = 0; q < 9; q++) {
        int idx = q * 256 + tid;
        if (idx < 1024) {
            int part = idx >> 9;               // 0: Ah, 1: Al
            int r = (idx & 511) >> 2, c = idx & 3;
            const __nv_bfloat16* src = (part ? Xl : Xh) + (size_t)(bm + r) * 320 + k0 + c * 8;
            int ok = (bm + r < M) ? 16 : 0;
            cp16(sb + part * A_TB + r * (MMS * 2) + c * 16, src, ok);
        } else if (idx < 2304) {
            int t = idx - 1024;
            int part = t >= 1280 / 2 ? 1 : 0;  // 0: Bh, 1: Bl (640 chunks each)
            int rr = t - part * 640;
            int r = rr >> 2, c = rr & 3;
            const __nv_bfloat16* src = (part ? Wl : Wh) + (size_t)(bn + r) * 320 + k0 + c * 8;
            cp16(sb + 2 * A_TB + part * B_TB + r * (MMS * 2) + c * 16, src, 16);
        }
    }
    CP_COMMIT();
}

__global__ __launch_bounds__(256, 2) void mgemm_kernel(const __nv_bfloat16* __restrict__ Xh,
                                                       const __nv_bfloat16* __restrict__ Xl,
                                                       const __nv_bfloat16* __restrict__ Wh,
                                                       const __nv_bfloat16* __restrict__ Wl,
                                                       float* __restrict__ C, int M, int mode,
                                                       const float* __restrict__ ep1,
                                                       const float* __restrict__ ep2,
                                                       const float* __restrict__ epv,
                                                       __nv_bfloat16* __restrict__ Oh,
                                                       __nv_bfloat16* __restrict__ Ol,
                                                       float* __restrict__ Z) {
    extern __shared__ char sm8[];
    uint32_t smb = smem_to_u32(sm8);
    int tid = threadIdx.x, wid = tid >> 5, lane = tid & 31;
    int bn = blockIdx.x * MMN, bm = blockIdx.y * 128;
    int wm = (wid >> 1) * 32;      // 4 m-groups of 32
    int wn = (wid & 1) * 80;       // 2 n-groups of 80

    float acc[2][10][4];
#pragma unroll
    for (int i = 0; i < 2; i++)
#pragma unroll
        for (int j = 0; j < 10; j++)
#pragma unroll
            for (int q = 0; q < 4; q++) acc[i][j][q] = 0.f;

    int aRow = lane & 15, aKsel = (lane >> 4) * 8;
    int bRow = (lane >> 4) * 8 + (lane & 7), bKsel = ((lane >> 3) & 1) * 8;

    mm_load_stage(smb, Xh, Xl, Wh, Wl, bm, bn, M, 0, tid);

    for (int ch = 0; ch < MM_CH; ch++) {
        uint32_t sb = smb + (ch & 1) * MM_STAGE;
        if (ch + 1 < MM_CH)
            mm_load_stage(smb + ((ch + 1) & 1) * MM_STAGE, Xh, Xl, Wh, Wl, bm, bn, M, (ch + 1) * MMK, tid);
        if (ch + 1 < MM_CH) cp_wait<1>(); else cp_wait<0>();
        __syncthreads();
#pragma unroll
        for (int ks = 0; ks < 2; ks++) {
            int k0 = ks * 16;
            uint32_t ah[2][4], al[2][4];
#pragma unroll
            for (int i = 0; i < 2; i++) {
                uint32_t ad = sb + ((wm + i * 16 + aRow) * MMS + k0 + aKsel) * 2;
                ldsm4(ah[i], ad);
                ldsm4(al[i], ad + A_TB);
            }
#pragma unroll
            for (int j = 0; j < 5; j++) {
                uint32_t bh[4], bl[4];
                uint32_t bd = sb + 2 * A_TB + ((wn + j * 16 + bRow) * MMS + k0 + bKsel) * 2;
                ldsm4(bh, bd);
                ldsm4(bl, bd + B_TB);
#pragma unroll
                for (int i = 0; i < 2; i++)
#pragma unroll
                    for (int t = 0; t < 2; t++) {
                        float* a4 = acc[i][j * 2 + t];
                        mma16816(a4, ah[i], bh[t * 2], bh[t * 2 + 1]);
                        mma16816(a4, ah[i], bl[t * 2], bl[t * 2 + 1]);
                        mma16816(a4, al[i], bh[t * 2], bh[t * 2 + 1]);
                    }
            }
        }
        __syncthreads();
    }

    // epilogue: warp covers rows [bm+wm, +32), cols [bn+wn, +80)
#pragma unroll
    for (int i = 0; i < 2; i++)
#pragma unroll
        for (int jj = 0; jj < 10; jj++) {
            int col = bn + wn + jj * 8 + (lane & 3) * 2;
#pragma unroll
            for (int half = 0; half < 2; half++) {
                int row = bm + wm + i * 16 + (lane >> 2) + half * 8;
                if (row >= M) continue;
                float v0 = acc[i][jj][half * 2], v1 = acc[i][jj][half * 2 + 1];
                float* crow = C + (size_t)row * SD + col;
                if (mode == 0) {
                    *(float2*)crow = make_float2(v0, v1);
                    if (Z) *(float2*)(Z + (size_t)row * SD + col) = make_float2(0.f, 0.f);
                } else {
                    const float* l1 = ep1 + (size_t)row * SD + col;
                    const float* gc = ep2 + (size_t)row * SD + col;
                    float2 a = *(const float2*)l1;
                    float2 g = *(const float2*)gc;
                    float o0 = 0.f, o1 = 0.f;
                    if (col < D_N) {
                        float tg = 1.0f / (1.0f + expf(-(v0 + epv[col])));
                        o0 = tg * fmaxf(g.x, 0.f) + (1.0f - tg) * a.x;
                    }
                    if (col + 1 < D_N) {
                        float tg = 1.0f / (1.0f + expf(-(v1 + epv[col + 1])));
                        o1 = tg * fmaxf(g.y, 0.f) + (1.0f - tg) * a.y;
                    }
                    *(float2*)crow = make_float2(o0, o1);
                    if (mode == 4) {
                        __nv_bfloat16 h0, h1, l0, l1b;
                        split2(o0, h0, l0);
                        split2(o1, h1, l1b);
                        __nv_bfloat162 hh, ll;
                        hh.x = h0; hh.y = h1;
                        ll.x = l0; ll.y = l1b;
                        *(__nv_bfloat162*)(Oh + (size_t)row * SD + col) = hh;
                        *(__nv_bfloat162*)(Ol + (size_t)row * SD + col) = ll;
                    }
                }
            }
        }
}

// ---------------- FFMA2 SGEMM (small R_N GEMMs) ----------------
#define BM 256
#define BN 64
#define BK 16
#define KTILES 19
__global__ __launch_bounds__(256, 2) void sgemm_kernel(const float* __restrict__ A,
                                                       const float* __restrict__ B,
                                                       float* __restrict__ C,
                                                       int M, int accumulate) {
    __shared__ float As[2][BK][BM];
    __shared__ float Bs[2][BK][BN];
    int bm = blockIdx.y * BM;
    int bn = blockIdx.x * BN;
    int tid = threadIdx.x;
    int tx = tid & 7;
    int ty = tid >> 3;
    int arow = bm + tid;
    bool avalid = arow < M;
    const float* Aptr = A + (size_t)arow * SD;
    int brow  = tid >> 4;
    int bcol4 = tid & 15;
    const float* Bptr = B + (size_t)brow * SD + bn + bcol4 * 4;

    unsigned long long acc[8][4];
#pragma unroll
    for (int i = 0; i < 8; i++)
#pragma unroll
        for (int j = 0; j < 4; j++) acc[i][j] = 0ull;

    float4 ra[4], rb;
#pragma unroll
    for (int c = 0; c < 4; c++)
        ra[c] = avalid ? *(const float4*)(Aptr + c * 4) : make_float4(0.f, 0.f, 0.f, 0.f);
    rb = *(const float4*)(Bptr);
#pragma unroll
    for (int c = 0; c < 4; c++) {
        As[0][c * 4 + 0][tid] = ra[c].x;
        As[0][c * 4 + 1][tid] = ra[c].y;
        As[0][c * 4 + 2][tid] = ra[c].z;
        As[0][c * 4 + 3][tid] = ra[c].w;
    }
    *(float4*)(&Bs[0][brow][bcol4 * 4]) = rb;
    __syncthreads();

    for (int t = 0; t < KTILES; t++) {
        int cur = t & 1, nxt = cur ^ 1;
        if (t + 1 < KTILES) {
            int k0 = (t + 1) * BK;
#pragma unroll
            for (int c = 0; c < 4; c++)
                ra[c] = avalid ? *(const float4*)(Aptr + k0 + c * 4) : make_float4(0.f, 0.f, 0.f, 0.f);
            rb = *(const float4*)(Bptr + (size_t)k0 * SD);
        }
#pragma unroll
        for (int k = 0; k < BK; k++) {
            ulonglong2 bb0 = *(const ulonglong2*)(&Bs[cur][k][tx * 8]);
            ulonglong2 bb1 = *(const ulonglong2*)(&Bs[cur][k][tx * 8 + 4]);
            unsigned long long b2[4] = {bb0.x, bb0.y, bb1.x, bb1.y};
            float4 a0 = *(const float4*)(&As[cur][k][ty * 8]);
            float4 a1 = *(const float4*)(&As[cur][k][ty * 8 + 4]);
            unsigned long long a2[8];
            a2[0] = bcast2(a0.x); a2[1] = bcast2(a0.y); a2[2] = bcast2(a0.z); a2[3] = bcast2(a0.w);
            a2[4] = bcast2(a1.x); a2[5] = bcast2(a1.y); a2[6] = bcast2(a1.z); a2[7] = bcast2(a1.w);
#pragma unroll
            for (int i = 0; i < 8; i++)
#pragma unroll
                for (int j = 0; j < 4; j++)
                    ffma2(acc[i][j], a2[i], b2[j]);
        }
        if (t + 1 < KTILES) {
#pragma unroll
            for (int c = 0; c < 4; c++) {
                As[nxt][c * 4 + 0][tid] = ra[c].x;
                As[nxt][c * 4 + 1][tid] = ra[c].y;
                As[nxt][c * 4 + 2][tid] = ra[c].z;
                As[nxt][c * 4 + 3][tid] = ra[c].w;
            }
            *(float4*)(&Bs[nxt][brow][bcol4 * 4]) = rb;
        }
        __syncthreads();
    }

    int gcol = bn + tx * 8;
#pragma unroll
    for (int i = 0; i < 8; i++) {
        int grow = bm + ty * 8 + i;
        if (grow >= M) continue;
        float2 u0 = unpack2(acc[i][0]);
        float2 u1 = unpack2(acc[i][1]);
        float2 u2 = unpack2(acc[i][2]);
        float2 u3 = unpack2(acc[i][3]);
        float* crow = C + (size_t)grow * SD + gcol;
        if (accumulate) {
            float4 c0 = *(float4*)crow;
            float4 c1 = *(float4*)(crow + 4);
            *(float4*)crow       = make_float4(c0.x + u0.x, c0.y + u0.y, c0.z + u1.x, c0.w + u1.y);
            *(float4*)(crow + 4) = make_float4(c1.x + u2.x, c1.y + u2.y, c1.z + u3.x, c1.w + u3.y);
        } else {
            *(float4*)crow       = make_float4(u0.x, u0.y, u1.x, u1.y);
            *(float4*)(crow + 4) = make_float4(u2.x, u2.y, u3.x, u3.y);
        }
    }
}

// h = emb + relu(h_pre + Bias); pads -> 0; also writes h splits to Ch/Cl.
__global__ void h_kernel(const float* __restrict__ Bias) {
    int i = blockIdx.x * blockDim.x + threadIdx.x;   // float4 index
    if (i >= E_N * SD4) return;
    int j = i % SD4;
    float4 o = make_float4(0.f, 0.f, 0.f, 0.f);
    if (j < D4) {
        float4 p = ((const float4*)g_A1)[i];
        float4 e = ((const float4*)g_emb)[i];
        int d = j * 4;
        o.x = e.x + fmaxf(p.x + Bias[d + 0], 0.f);
        o.y = e.y + fmaxf(p.y + Bias[d + 1], 0.f);
        o.z = e.z + fmaxf(p.z + Bias[d + 2], 0.f);
        o.w = e.w + fmaxf(p.w + Bias[d + 3], 0.f);
    }
    ((float4*)g_A2)[i] = o;
    float xs[4] = {o.x, o.y, o.z, o.w};
    __nv_bfloat16 h[4], l[4];
#pragma unroll
    for (int q = 0; q < 4; q++) split2(xs[q], h[q], l[q]);
    __nv_bfloat162 h0, h1, l0, l1;
    h0.x = h[0]; h0.y = h[1]; h1.x = h[2]; h1.y = h[3];
    l0.x = l[0]; l0.y = l[1]; l1.x = l[2]; l1.y = l[3];
    ((__nv_bfloat162*)g_Ch)[2 * i]     = h0;
    ((__nv_bfloat162*)g_Ch)[2 * i + 1] = h1;
    ((__nv_bfloat162*)g_Cl)[2 * i]     = l0;
    ((__nv_bfloat162*)g_Cl)[2 * i + 1] = l1;
}

// Fused hinge loss: one block per pair t.
__global__ __launch_bounds__(256) void loss_kernel(const int* __restrict__ pl,
                                                   const int* __restrict__ pr,
                                                   const int* __restrict__ nr,
                                                   const int* __restrict__ nl,
                                                   const float* __restrict__ mask,
                                                   const float* __restrict__ node,
                                                   float* __restrict__ out) {
    __shared__ float4 sl[D4], sr[D4];
    __shared__ float wpart[8];
    __shared__ float s_dm;
    int t    = blockIdx.x;
    int tid  = threadIdx.x;
    int lane = tid & 31;
    int wid  = tid >> 5;

    const float4* xl = (const float4*)(node + (size_t)pl[t] * SD);
    const float4* xr = (const float4*)(node + (size_t)pr[t] * SD);
    float d = 0.f;
    if (tid < D4) {
        float4 a = xl[tid], b = xr[tid];
        sl[tid] = a; sr[tid] = b;
        d = fabsf(a.x - b.x) + fabsf(a.y - b.y) + fabsf(a.z - b.z) + fabsf(a.w - b.w);
    }
    d = warp_sum(d);
    if (lane == 0) wpart[wid] = d;
    __syncthreads();
    if (tid == 0) s_dm = wpart[0] + wpart[1] + wpart[2] + GAMMA_F;
    __syncthreads();
    float dm = s_dm;

    float hsum = 0.f;
    for (int k = wid; k < K_N; k += 8) {
        int i = t * K_N + k;
        const float4* xR = (const float4*)(node + (size_t)nr[i] * SD);
        const float4* xL = (const float4*)(node + (size_t)nl[i] * SD);
        float s1 = 0.f, s2 = 0.f;
#pragma unroll
        for (int it = 0; it < 3; it++) {
            int j = lane + it * 32;
            if (j < D4) {
                float4 a = sl[j], b = sr[j], cr = xR[j], cl = xL[j];
                s1 += fabsf(a.x - cr.x) + fabsf(a.y - cr.y) + fabsf(a.z - cr.z) + fabsf(a.w - cr.w);
                s2 += fabsf(cl.x - b.x) + fabsf(cl.y - b.y) + fabsf(cl.z - b.z) + fabsf(cl.w - b.w);
            }
        }
        s1 = warp_sum(s1);
        s2 = warp_sum(s2);
        if (lane == 0) hsum += (fmaxf(dm - s1, 0.f) + fmaxf(dm - s2, 0.f)) * mask[i];
    }
    if (lane == 0) wpart[wid] = hsum;
    __syncthreads();
    if (tid == 0) {
        float tot = 0.f;
#pragma unroll
        for (int w = 0; w < 8; w++) tot += wpart[w];
        atomicAdd(out, tot * 0.5f);
    }
}

// ---------------- host ----------------
extern "C" void kernel_launch(void* const* d_in, const int* in_sizes, int n_in,
                              void* d_out, int out_size) {
    const float* we    = (const float*)d_in[0];
    const float* kgw   = (const float*)d_in[1];
    const float* bg    = (const float*)d_in[2];
    const float* W1    = (const float*)d_in[3];
    const float* W2    = (const float*)d_in[4];
    const float* Dense = (const float*)d_in[5];
    const float* Bias  = (const float*)d_in[6];
    const int*   hr_rows = (const int*)d_in[7];
    const int*   hr_cols = (const int*)d_in[8];
    const float* hr_vals = (const float*)d_in[9];
    const int*   tr_rows = (const int*)d_in[10];
    const int*   tr_cols = (const int*)d_in[11];
    const float* tr_vals = (const float*)d_in[12];
    const int*   er_rows = (const int*)d_in[13];
    const int*   er_cols = (const int*)d_in[14];
    const float* er_vals = (const float*)d_in[15];
    const int*   adj_rows = (const int*)d_in[16];
    const int*   adj_cols = (const int*)d_in[17];
    const float* adj_vals = (const float*)d_in[18];
    const int*   pos_left  = (const int*)d_in[19];
    const int*   pos_right = (const int*)d_in[20];
    const int*   neg_right = (const int*)d_in[21];
    const int*   neg_left  = (const int*)d_in[22];
    const float* mask      = (const float*)d_in[23];
    float* out = (float*)d_out;

    int nnz_hr  = in_sizes[7];
    int nnz_tr  = in_sizes[10];
    int nnz_er  = in_sizes[13];
    int nnz_adj = in_sizes[16];

    float *p_emb, *p_A1, *p_A2, *p_A3, *p_A5, *p_A6, *p_Lm, *p_Rm, *p_P, *p_Wt;
    __nv_bfloat16 *p_Bh, *p_Bl, *p_Ch, *p_Cl, *p_WTh, *p_WTl;
    cudaGetSymbolAddress((void**)&p_emb, g_emb);
    cudaGetSymbolAddress((void**)&p_A1,  g_A1);
    cudaGetSymbolAddress((void**)&p_A2,  g_A2);
    cudaGetSymbolAddress((void**)&p_A3,  g_A3);
    cudaGetSymbolAddress((void**)&p_A5,  g_A5);
    cudaGetSymbolAddress((void**)&p_A6,  g_A6);
    cudaGetSymbolAddress((void**)&p_Lm,  g_Lm);
    cudaGetSymbolAddress((void**)&p_Rm,  g_Rm);
    cudaGetSymbolAddress((void**)&p_P,   g_P);
    cudaGetSymbolAddress((void**)&p_Wt,  g_Wt);
    cudaGetSymbolAddress((void**)&p_Bh,  g_Bh);
    cudaGetSymbolAddress((void**)&p_Bl,  g_Bl);
    cudaGetSymbolAddress((void**)&p_Ch,  g_Ch);
    cudaGetSymbolAddress((void**)&p_Cl,  g_Cl);
    cudaGetSymbolAddress((void**)&p_WTh, g_WTh);
    cudaGetSymbolAddress((void**)&p_WTl, g_WTl);

    cudaFuncSetAttribute(mgemm_kernel, cudaFuncAttributeMaxDynamicSharedMemorySize, MM_SMEM);

    dim3 mmGrid(SD / MMN, (E_N + 127) / 128);       // (2, 782)
    dim3 gemmGridR(SD / BN, (R_N + BM - 1) / BM);

    // 1-3, then launch #4 = first HMMA GEMM (profiled)
    wsplit_kernel<<<(4 * WOFF + 255) / 256, 256>>>(Dense, W1, W2, kgw);
    normalize_kernel<<<(E_N * 32) / 256, 256>>>(we);
    zero4_kernel<<<(R_N * SD / 4 + 255) / 256, 256>>>((float4*)p_Lm, R_N * SD / 4);
    mgemm_kernel<<<mmGrid, 256, MM_SMEM>>>(p_Bh, p_Bl, p_WTh, p_WTl, p_A1, E_N, 0, 0, 0, 0, 0, 0, 0);

    // relation aggregation
    zero4_kernel<<<(R_N * SD / 4 + 255) / 256, 256>>>((float4*)p_Rm, R_N * SD / 4);
    spmm_kernel<<<(nnz_hr + 7) / 8, 256>>>(hr_rows, hr_cols, hr_vals, nnz_hr, p_emb, p_Lm, 0);
    spmm_kernel<<<(nnz_tr + 7) / 8, 256>>>(tr_rows, tr_cols, tr_vals, nnz_tr, p_emb, p_Rm, 0);

    // P = L @ Db1 + Rm @ Db2
    pad_weights_kernel<<<(2 * SD * SD + 255) / 256, 256>>>(Dense);
    sgemm_kernel<<<gemmGridR, 256>>>(p_Lm, p_Wt, p_P, R_N, 0);
    sgemm_kernel<<<gemmGridR, 256>>>(p_Rm, p_Wt + SD * SD, p_P, R_N, 1);

    // h_pre += spmm(er, +-P)
    spmm_kernel<<<(nnz_er + 7) / 8, 256>>>(er_rows, er_cols, er_vals, nnz_er, p_P, p_A1, 1);

    zero_out_kernel<<<1, 1>>>(out);

    // h = emb + relu(h_pre + Bias)  (+ h splits -> Ch/Cl)
    h_kernel<<<(E_N * SD4 + 255) / 256, 256>>>(Bias);

    // layer 1: t1 = h@W1 -> A3 (also zeroes A5); gcn1 -> A5; gate GEMM fuses highway -> A6 (+ splits -> Bh/Bl)
    mgemm_kernel<<<mmGrid, 256, MM_SMEM>>>(p_Ch, p_Cl, p_WTh + 1 * WOFF, p_WTl + 1 * WOFF, p_A3, E_N, 0, 0, 0, 0, 0, 0, p_A5);
    spmm_kernel<<<(nnz_adj + 7) / 8, 256>>>(adj_rows, adj_cols, adj_vals, nnz_adj, p_A3, p_A5, 0);
    mgemm_kernel<<<mmGrid, 256, MM_SMEM>>>(p_Ch, p_Cl, p_WTh + 3 * WOFF, p_WTl + 3 * WOFF, p_A6, E_N, 4, p_A2, p_A5, bg, p_Bh, p_Bl, 0);

    // layer 2: t2 = hg1@W2 -> A3 (also zeroes A1); gcn2 -> A1; gate GEMM fuses highway -> node (A2)
    mgemm_kernel<<<mmGrid, 256, MM_SMEM>>>(p_Bh, p_Bl, p_WTh + 2 * WOFF, p_WTl + 2 * WOFF, p_A3, E_N, 0, 0, 0, 0, 0, 0, p_A1);
    spmm_kernel<<<(nnz_adj + 7) / 8, 256>>>(adj_rows, adj_cols, adj_vals, nnz_adj, p_A3, p_A1, 0);
    mgemm_kernel<<<mmGrid, 256, MM_SMEM>>>(p_Bh, p_Bl, p_WTh + 3 * WOFF, p_WTl + 3 * WOFF, p_A2, E_N, 3, p_A6, p_A1, bg, 0, 0, 0);

    // fused loss
    loss_kernel<<<T_N, 256>>>(pos_left, pos_right, neg_right, neg_left, mask, p_A2, out);
    (void)n_in; (void)out_size;
}

// round 14
// speedup vs baseline: 1.9864x; 1.1050x over previous
#include <cuda_runtime.h>
#include <cuda_bf16.h>
#include <math.h>
#include <stdint.h>

#define E_N 100000
#define D_N 300
#define R_N 1000
#define T_N 10000
#define K_N 25
#define SD  320
#define D4  75
#define SD4 80
#define GAMMA_F 1.0f
#define WOFF (320*320)
#define NNZ_ADJ 600000
#define NNZ_ER  300000

// ---------------- scratch (device globals: allocation-free) ----------------
__device__ float g_emb[(size_t)E_N * SD];
__device__ float g_A1 [(size_t)E_N * SD];
__device__ float g_A2 [(size_t)E_N * SD];
__device__ float g_A3 [(size_t)E_N * SD];
__device__ float g_A5 [(size_t)E_N * SD];
__device__ float g_A6 [(size_t)E_N * SD];
__device__ float g_Lm [R_N * SD];
__device__ float g_Rm [R_N * SD];
__device__ float g_P  [R_N * SD];
__device__ float g_Wt [2 * SD * SD];
__device__ __nv_bfloat16 g_Bh[(size_t)E_N * SD];  // split pair A (emb, then hg1)
__device__ __nv_bfloat16 g_Bl[(size_t)E_N * SD];
__device__ __nv_bfloat16 g_Ch[(size_t)E_N * SD];  // split pair B (h)
__device__ __nv_bfloat16 g_Cl[(size_t)E_N * SD];
__device__ __nv_bfloat16 g_WTh[4 * WOFF];         // transposed weights hi: 0:Dt 1:W1 2:W2 3:KG
__device__ __nv_bfloat16 g_WTl[4 * WOFF];
// CSR scratch
__device__ int g_adj_ptr[E_N + 1];
__device__ int g_adj_cur[E_N];
__device__ int g_adj_perm[NNZ_ADJ];
__device__ int g_er_ptr[E_N + 1];
__device__ int g_er_cur[E_N];
__device__ int g_er_perm[NNZ_ER];
__device__ int g_bsum[256];

// ---------------- helpers ----------------
__device__ __forceinline__ uint32_t smem_to_u32(const void* p) {
    uint32_t a;
    asm("{ .reg .u64 t; cvta.to.shared.u64 t, %1; cvt.u32.u64 %0, t; }" : "=r"(a) : "l"(p));
    return a;
}
__device__ __forceinline__ float warp_sum(float v) {
#pragma unroll
    for (int o = 16; o > 0; o >>= 1) v += __shfl_xor_sync(0xffffffffu, v, o);
    return v;
}
__device__ __forceinline__ int warp_sum_i(int v) {
#pragma unroll
    for (int o = 16; o > 0; o >>= 1) v += __shfl_xor_sync(0xffffffffu, v, o);
    return v;
}
__device__ __forceinline__ unsigned long long bcast2(float x) {
    unsigned long long r;
    asm("mov.b64 %0, {%1, %1};" : "=l"(r) : "f"(x));
    return r;
}
__device__ __forceinline__ float2 unpack2(unsigned long long v) {
    float2 f;
    asm("mov.b64 {%0, %1}, %2;" : "=f"(f.x), "=f"(f.y) : "l"(v));
    return f;
}
__device__ __forceinline__ void ffma2(unsigned long long& d, unsigned long long a, unsigned long long b) {
    asm("fma.rn.f32x2 %0, %1, %2, %0;" : "+l"(d) : "l"(a), "l"(b));
}
__device__ __forceinline__ void red_add_v4(float* p, float a, float b, float c, float d) {
    asm volatile("red.global.add.v4.f32 [%0], {%1, %2, %3, %4};"
                 :: "l"(p), "f"(a), "f"(b), "f"(c), "f"(d) : "memory");
}
__device__ __forceinline__ void cp16(uint32_t dst, const void* src, int src_bytes) {
    asm volatile("cp.async.cg.shared.global [%0], [%1], 16, %2;"
                 :: "r"(dst), "l"(src), "r"(src_bytes) : "memory");
}
#define CP_COMMIT() asm volatile("cp.async.commit_group;" ::: "memory")
template <int N>
__device__ __forceinline__ void cp_wait() {
    asm volatile("cp.async.wait_group %0;" :: "n"(N) : "memory");
}
__device__ __forceinline__ void ldsm4(uint32_t* r, uint32_t addr) {
    asm volatile("ldmatrix.sync.aligned.m8n8.x4.shared.b16 {%0,%1,%2,%3}, [%4];"
                 : "=r"(r[0]), "=r"(r[1]), "=r"(r[2]), "=r"(r[3]) : "r"(addr));
}
__device__ __forceinline__ void mma16816(float* d, const uint32_t* a, uint32_t b0, uint32_t b1) {
    asm volatile("mma.sync.aligned.m16n8k16.row.col.f32.bf16.bf16.f32 "
                 "{%0,%1,%2,%3}, {%4,%5,%6,%7}, {%8,%9}, {%0,%1,%2,%3};"
                 : "+f"(d[0]), "+f"(d[1]), "+f"(d[2]), "+f"(d[3])
                 : "r"(a[0]), "r"(a[1]), "r"(a[2]), "r"(a[3]), "r"(b0), "r"(b1));
}
__device__ __forceinline__ void split2(float v, __nv_bfloat16& h, __nv_bfloat16& l) {
    h = __float2bfloat16_rn(v);
    l = __float2bfloat16_rn(v - __bfloat162float(h));
}

// ---------------- CSR build kernels ----------------
__global__ void zcnt_kernel(int* cnt, int n) {
    int i = blockIdx.x * blockDim.x + threadIdx.x;
    if (i < n) cnt[i] = 0;
}
__global__ void hist_kernel(const int* __restrict__ rows, int nnz, int* cnt) {
    int i = blockIdx.x * blockDim.x + threadIdx.x;
    if (i < nnz) atomicAdd(&cnt[rows[i]], 1);
}
// block sums over chunks of 1024
__global__ void scan1_kernel(const int* __restrict__ cnt, int n, int* bsum) {
    __shared__ int sh[8];
    int t = threadIdx.x, base = blockIdx.x * 1024 + t * 4;
    int s = 0;
#pragma unroll
    for (int q = 0; q < 4; q++) if (base + q < n) s += cnt[base + q];
    s = warp_sum_i(s);
    if ((t & 31) == 0) sh[t >> 5] = s;
    __syncthreads();
    if (t == 0) {
        int tot = 0;
#pragma unroll
        for (int w = 0; w < 8; w++) tot += sh[w];
        bsum[blockIdx.x] = tot;
    }
}
__global__ void scan2_kernel(int* bsum, int nb) {
    if (threadIdx.x == 0 && blockIdx.x == 0) {
        int run = 0;
        for (int i = 0; i < nb; i++) { int v = bsum[i]; bsum[i] = run; run += v; }
    }
}
// exclusive scan within chunk + global offset; writes rowptr, cursor, and rowptr[n]
__global__ void scan3_kernel(const int* __restrict__ cnt, const int* __restrict__ bsum,
                             int n, int* rowptr, int* cursor) {
    __shared__ int ts[256];
    int t = threadIdx.x, b = blockIdx.x;
    int base = b * 1024 + t * 4;
    int v[4], s = 0;
#pragma unroll
    for (int q = 0; q < 4; q++) { v[q] = (base + q < n) ? cnt[base + q] : 0; s += v[q]; }
    ts[t] = s;
    __syncthreads();
#pragma unroll
    for (int off = 1; off < 256; off <<= 1) {
        int x = (t >= off) ? ts[t - off] : 0;
        __syncthreads();
        ts[t] += x;
        __syncthreads();
    }
    int pre = bsum[b] + (t ? ts[t - 1] : 0);
#pragma unroll
    for (int q = 0; q < 4; q++) {
        int i = base + q;
        if (i < n) {
            rowptr[i] = pre;
            cursor[i] = pre;
            pre += v[q];
            if (i == n - 1) rowptr[n] = pre;
        }
    }
}
__global__ void scatter_kernel(const int* __restrict__ rows, int nnz, int* cursor, int* perm) {
    int i = blockIdx.x * blockDim.x + threadIdx.x;
    if (i < nnz) {
        int pos = atomicAdd(&cursor[rows[i]], 1);
        perm[pos] = i;
    }
}

// ---------------- small kernels ----------------
__global__ void zero_out_kernel(float* out) { if (threadIdx.x == 0 && blockIdx.x == 0) out[0] = 0.0f; }

__global__ void zero4_kernel(float4* p, int n4) {
    int i = blockIdx.x * blockDim.x + threadIdx.x;
    if (i < n4) p[i] = make_float4(0.f, 0.f, 0.f, 0.f);
}

__global__ void pad_weights_kernel(const float* __restrict__ Dense) {
    int idx = blockIdx.x * blockDim.x + threadIdx.x;
    if (idx >= 2 * SD * SD) return;
    int w = idx / (SD * SD);
    int rem = idx % (SD * SD);
    int r = rem / SD, c = rem % SD;
    float v = 0.f;
    if (r < D_N && c < D_N) v = Dense[(size_t)(D_N * (1 + w) + r) * D_N + c];
    g_Wt[idx] = v;
}

__global__ void wsplit_kernel(const float* __restrict__ Dense, const float* __restrict__ W1,
                              const float* __restrict__ W2, const float* __restrict__ KG) {
    int idx = blockIdx.x * blockDim.x + threadIdx.x;
    if (idx >= 4 * WOFF) return;
    int w = idx / WOFF;
    int rem = idx % WOFF;
    int n = rem / 320, k = rem % 320;
    float v = 0.f;
    if (n < D_N && k < D_N) {
        const float* src = (w == 0) ? Dense : (w == 1) ? W1 : (w == 2) ? W2 : KG;
        v = src[(size_t)k * D_N + n];
    }
    __nv_bfloat16 hi, lo;
    split2(v, hi, lo);
    g_WTh[idx] = hi;
    g_WTl[idx] = lo;
}

// normalize + emb splits (to Bh/Bl). Warp per row.
__global__ void normalize_kernel(const float* __restrict__ we) {
    int warp = (blockIdx.x * blockDim.x + threadIdx.x) >> 5;
    int lane = threadIdx.x & 31;
    if (warp >= E_N) return;
    const float4* src = (const float4*)(we + (size_t)warp * D_N);
    float4 v[3];
    float s = 0.f;
#pragma unroll
    for (int it = 0; it < 3; it++) {
        int j = lane + it * 32;
        if (j < D4) {
            float4 x = src[j];
            v[it] = x;
            s += x.x * x.x + x.y * x.y + x.z * x.z + x.w * x.w;
        } else v[it] = make_float4(0.f, 0.f, 0.f, 0.f);
    }
    s = warp_sum(s);
    float inv = 1.0f / sqrtf(s);
    float4* dst = (float4*)(g_emb + (size_t)warp * SD);
    __nv_bfloat162* bh = (__nv_bfloat162*)(g_Bh + (size_t)warp * SD);
    __nv_bfloat162* bl = (__nv_bfloat162*)(g_Bl + (size_t)warp * SD);
#pragma unroll
    for (int it = 0; it < 3; it++) {
        int j = lane + it * 32;
        if (j < SD4) {
            float4 o = make_float4(0.f, 0.f, 0.f, 0.f);
            if (j < D4) o = make_float4(v[it].x * inv, v[it].y * inv, v[it].z * inv, v[it].w * inv);
            dst[j] = o;
            float xs[4] = {o.x, o.y, o.z, o.w};
            __nv_bfloat16 h[4], l[4];
#pragma unroll
            for (int q = 0; q < 4; q++) split2(xs[q], h[q], l[q]);
            __nv_bfloat162 h0, h1, l0, l1;
            h0.x = h[0]; h0.y = h[1]; h1.x = h[2]; h1.y = h[3];
            l0.x = l[0]; l0.y = l[1]; l1.x = l[2]; l1.y = l[3];
            bh[2 * j] = h0; bh[2 * j + 1] = h1;
            bl[2 * j] = l0; bl[2 * j + 1] = l1;
        }
    }
}

// COO SpMM scatter (hr/tr only). Warp per nnz.
__global__ void spmm_kernel(const int* __restrict__ rows, const int* __restrict__ cols,
                            const float* __restrict__ vals, int nnz,
                            const float* __restrict__ X, float* __restrict__ Out) {
    int warp = (blockIdx.x * blockDim.x + threadIdx.x) >> 5;
    int lane = threadIdx.x & 31;
    if (warp >= nnz) return;
    int   r = rows[warp];
    int   c = cols[warp];
    float v = vals[warp];
    const float4* xr = (const float4*)(X + (size_t)c * SD);
    float* orow = Out + (size_t)r * SD;
#pragma unroll
    for (int it = 0; it < 3; it++) {
        int j = lane + it * 32;
        if (j < D4) {
            float4 x = xr[j];
            red_add_v4(orow + j * 4, v * x.x, v * x.y, v * x.z, v * x.w);
        }
    }
}

// CSR gather SpMM: warp per output row, no atomics. Out[r] = sum vals * X[cols].
__global__ void gspmm_kernel(const int* __restrict__ rowptr, const int* __restrict__ perm,
                             const int* __restrict__ cols, const float* __restrict__ vals,
                             const float* __restrict__ X, float* __restrict__ Out, int n_rows) {
    int warp = (blockIdx.x * blockDim.x + threadIdx.x) >> 5;
    int lane = threadIdx.x & 31;
    if (warp >= n_rows) return;
    int s = rowptr[warp], e = rowptr[warp + 1];
    float4 a0 = make_float4(0.f, 0.f, 0.f, 0.f);
    float4 a1 = a0, a2 = a0;
    for (int idx = s; idx < e; idx++) {
        int i = perm[idx];
        int c = cols[i];
        float v = vals[i];
        const float4* xr = (const float4*)(X + (size_t)c * SD);
        float4 x0 = xr[lane], x1 = xr[lane + 32];
        a0.x += v * x0.x; a0.y += v * x0.y; a0.z += v * x0.z; a0.w += v * x0.w;
        a1.x += v * x1.x; a1.y += v * x1.y; a1.z += v * x1.z; a1.w += v * x1.w;
        if (lane < 11) {
            float4 x2 = xr[lane + 64];
            a2.x += v * x2.x; a2.y += v * x2.y; a2.z += v * x2.z; a2.w += v * x2.w;
        }
    }
    float4* o = (float4*)(Out + (size_t)warp * SD);
    o[lane] = a0;
    o[lane + 32] = a1;
    if (lane < 11) o[lane + 64] = a2;
}

// Fused: h = emb + relu(A1 + er_gather(+-P) + Bias); writes h -> A2 and splits -> Ch/Cl.
// Warp per row. Pads (j 75..79) zeroed.
__global__ void h_er_kernel(const int* __restrict__ rowptr, const int* __restrict__ perm,
                            const int* __restrict__ cols, const float* __restrict__ vals,
                            const float* __restrict__ Bias) {
    int warp = (blockIdx.x * blockDim.x + threadIdx.x) >> 5;
    int lane = threadIdx.x & 31;
    if (warp >= E_N) return;
    const float4* pr = (const float4*)(g_A1 + (size_t)warp * SD);
    float4 a0 = pr[lane], a1 = pr[lane + 32];
    float4 a2 = make_float4(0.f, 0.f, 0.f, 0.f);
    if (lane < 11) a2 = pr[lane + 64];
    int s = rowptr[warp], e = rowptr[warp + 1];
    for (int idx = s; idx < e; idx++) {
        int i = perm[idx];
        int c = cols[i];
        float v = vals[i];
        if (c >= R_N) { c -= R_N; v = -v; }
        const float4* xr = (const float4*)(g_P + (size_t)c * SD);
        float4 x0 = xr[lane], x1 = xr[lane + 32];
        a0.x += v * x0.x; a0.y += v * x0.y; a0.z += v * x0.z; a0.w += v * x0.w;
        a1.x += v * x1.x; a1.y += v * x1.y; a1.z += v * x1.z; a1.w += v * x1.w;
        if (lane < 11) {
            float4 x2 = xr[lane + 64];
            a2.x += v * x2.x; a2.y += v * x2.y; a2.z += v * x2.z; a2.w += v * x2.w;
        }
    }
    const float4* er = (const float4*)(g_emb + (size_t)warp * SD);
    float4* ho = (float4*)(g_A2 + (size_t)warp * SD);
    __nv_bfloat162* ch = (__nv_bfloat162*)(g_Ch + (size_t)warp * SD);
    __nv_bfloat162* cl = (__nv_bfloat162*)(g_Cl + (size_t)warp * SD);
    float4 accs[3] = {a0, a1, a2};
#pragma unroll
    for (int it = 0; it < 3; it++) {
        int j = lane + it * 32;
        if (j >= SD4) continue;
        float4 o = make_float4(0.f, 0.f, 0.f, 0.f);
        if (j < D4) {
            float4 em = er[j];
            float4 a = accs[it];
            int d = j * 4;
            o.x = em.x + fmaxf(a.x + Bias[d + 0], 0.f);
            o.y = em.y + fmaxf(a.y + Bias[d + 1], 0.f);
            o.z = em.z + fmaxf(a.z + Bias[d + 2], 0.f);
            o.w = em.w + fmaxf(a.w + Bias[d + 3], 0.f);
        }
        ho[j] = o;
        float xs[4] = {o.x, o.y, o.z, o.w};
        __nv_bfloat16 h[4], l[4];
#pragma unroll
        for (int q = 0; q < 4; q++) split2(xs[q], h[q], l[q]);
        __nv_bfloat162 h0, h1, l0, l1;
        h0.x = h[0]; h0.y = h[1]; h1.x = h[2]; h1.y = h[3];
        l0.x = l[0]; l0.y = l[1]; l1.x = l[2]; l1.y = l[3];
        ch[2 * j] = h0; ch[2 * j + 1] = h1;
        cl[2 * j] = l0; cl[2 * j + 1] = l1;
    }
}

// ---------------- HMMA GEMM (bf16 split-2): C[M,320] = X @ W ----------------
#define MMN 160
#define MMK 32
#define MMS 40
#define A_TB (128 * MMS * 2)
#define B_TB (MMN * MMS * 2)
#define MM_STAGE (2 * A_TB + 2 * B_TB)
#define MM_SMEM  (2 * MM_STAGE)
#define MM_CH 10

__device__ __forceinline__ void mm_load_stage(uint32_t sb,
                                              const __nv_bfloat16* Xh, const __nv_bfloat16* Xl,
                                              const __nv_bfloat16* Wh, const __nv_bfloat16* Wl,
                                              int bm, int bn, int M, int k0, int tid) {
#pragma unroll
    for (int q = 0; q < 9; q++) {
        int idx = q * 256 + tid;
        if (idx < 1024) {
            int part = idx >> 9;
            int r = (idx & 511) >> 2, c = idx & 3;
            const __nv_bfloat16* src = (part ? Xl : Xh) + (size_t)(bm + r) * 320 + k0 + c * 8;
            int ok = (bm + r < M) ? 16 : 0;
            cp16(sb + part * A_TB + r * (MMS * 2) + c * 16, src, ok);
        } else if (idx < 2304) {
            int t = idx - 1024;
            int part = t >= 640 ? 1 : 0;
            int rr = t - part * 640;
            int r = rr >> 2, c = rr & 3;
            const __nv_bfloat16* src = (part ? Wl : Wh) + (size_t)(bn + r) * 320 + k0 + c * 8;
            cp16(sb + 2 * A_TB + part * B_TB + r * (MMS * 2) + c * 16, src, 16);
        }
    }
    CP_COMMIT();
}

__global__ __launch_bounds__(256, 2) void mgemm_kernel(const __nv_bfloat16* __restrict__ Xh,
                                                       const __nv_bfloat16* __restrict__ Xl,
                                                       const __nv_bfloat16* __restrict__ Wh,
                                                       const __nv_bfloat16* __restrict__ Wl,
                                                       float* __restrict__ C, int M, int mode,
                                                       const float* __restrict__ ep1,
                                                       const float* __restrict__ ep2,
                                                       const float* __restrict__ epv,
                                                       __nv_bfloat16* __restrict__ Oh,
                                                       __nv_bfloat16* __restrict__ Ol) {
    extern __shared__ char sm8[];
    uint32_t smb = smem_to_u32(sm8);
    int tid = threadIdx.x, wid = tid >> 5, lane = tid & 31;
    int bn = blockIdx.x * MMN, bm = blockIdx.y * 128;
    int wm = (wid >> 1) * 32;
    int wn = (wid & 1) * 80;

    float acc[2][10][4];
#pragma unroll
    for (int i = 0; i < 2; i++)
#pragma unroll
        for (int j = 0; j < 10; j++)
#pragma unroll
            for (int q = 0; q < 4; q++) acc[i][j][q] = 0.f;

    int aRow = lane & 15, aKsel = (lane >> 4) * 8;
    int bRow = (lane >> 4) * 8 + (lane & 7), bKsel = ((lane >> 3) & 1) * 8;

    mm_load_stage(smb, Xh, Xl, Wh, Wl, bm, bn, M, 0, tid);

    for (int ch = 0; ch < MM_CH; ch++) {
        uint32_t sb = smb + (ch & 1) * MM_STAGE;
        if (ch + 1 < MM_CH)
            mm_load_stage(smb + ((ch + 1) & 1) * MM_STAGE, Xh, Xl, Wh, Wl, bm, bn, M, (ch + 1) * MMK, tid);
        if (ch + 1 < MM_CH) cp_wait<1>(); else cp_wait<0>();
        __syncthreads();
#pragma unroll
        for (int ks = 0; ks < 2; ks++) {
            int k0 = ks * 16;
            uint32_t ah[2][4], al[2][4];
#pragma unroll
            for (int i = 0; i < 2; i++) {
                uint32_t ad = sb + ((wm + i * 16 + aRow) * MMS + k0 + aKsel) * 2;
                ldsm4(ah[i], ad);
                ldsm4(al[i], ad + A_TB);
            }
#pragma unroll
            for (int j = 0; j < 5; j++) {
                uint32_t bh[4], bl[4];
                uint32_t bd = sb + 2 * A_TB + ((wn + j * 16 + bRow) * MMS + k0 + bKsel) * 2;
                ldsm4(bh, bd);
                ldsm4(bl, bd + B_TB);
#pragma unroll
                for (int i = 0; i < 2; i++)
#pragma unroll
                    for (int t = 0; t < 2; t++) {
                        float* a4 = acc[i][j * 2 + t];
                        mma16816(a4, ah[i], bh[t * 2], bh[t * 2 + 1]);
                        mma16816(a4, ah[i], bl[t * 2], bl[t * 2 + 1]);
                        mma16816(a4, al[i], bh[t * 2], bh[t * 2 + 1]);
                    }
            }
        }
        __syncthreads();
    }

#pragma unroll
    for (int i = 0; i < 2; i++)
#pragma unroll
        for (int jj = 0; jj < 10; jj++) {
            int col = bn + wn + jj * 8 + (lane & 3) * 2;
#pragma unroll
            for (int half = 0; half < 2; half++) {
                int row = bm + wm + i * 16 + (lane >> 2) + half * 8;
                if (row >= M) continue;
                float v0 = acc[i][jj][half * 2], v1 = acc[i][jj][half * 2 + 1];
                float* crow = C + (size_t)row * SD + col;
                if (mode == 0) {
                    *(float2*)crow = make_float2(v0, v1);
                } else {
                    const float* l1 = ep1 + (size_t)row * SD + col;
                    const float* gc = ep2 + (size_t)row * SD + col;
                    float2 a = *(const float2*)l1;
                    float2 g = *(const float2*)gc;
                    float o0 = 0.f, o1 = 0.f;
                    if (col < D_N) {
                        float tg = 1.0f / (1.0f + expf(-(v0 + epv[col])));
                        o0 = tg * fmaxf(g.x, 0.f) + (1.0f - tg) * a.x;
                    }
                    if (col + 1 < D_N) {
                        float tg = 1.0f / (1.0f + expf(-(v1 + epv[col + 1])));
                        o1 = tg * fmaxf(g.y, 0.f) + (1.0f - tg) * a.y;
                    }
                    *(float2*)crow = make_float2(o0, o1);
                    if (mode == 4) {
                        __nv_bfloat16 h0, h1, l0, l1b;
                        split2(o0, h0, l0);
                        split2(o1, h1, l1b);
                        __nv_bfloat162 hh, ll;
                        hh.x = h0; hh.y = h1;
                        ll.x = l0; ll.y = l1b;
                        *(__nv_bfloat162*)(Oh + (size_t)row * SD + col) = hh;
                        *(__nv_bfloat162*)(Ol + (size_t)row * SD + col) = ll;
                    }
                }
            }
        }
}

// ---------------- FFMA2 SGEMM (small R_N GEMMs) ----------------
#define BM 256
#define BN 64
#define BK 16
#define KTILES 19
__global__ __launch_bounds__(256, 2) void sgemm_kernel(const float* __restrict__ A,
                                                       const float* __restrict__ B,
                                                       float* __restrict__ C,
                                                       int M, int accumulate) {
    __shared__ float As[2][BK][BM];
    __shared__ float Bs[2][BK][BN];
    int bm = blockIdx.y * BM;
    int bn = blockIdx.x * BN;
    int tid = threadIdx.x;
    int tx = tid & 7;
    int ty = tid >> 3;
    int arow = bm + tid;
    bool avalid = arow < M;
    const float* Aptr = A + (size_t)arow * SD;
    int brow  = tid >> 4;
    int bcol4 = tid & 15;
    const float* Bptr = B + (size_t)brow * SD + bn + bcol4 * 4;

    unsigned long long acc[8][4];
#pragma unroll
    for (int i = 0; i < 8; i++)
#pragma unroll
        for (int j = 0; j < 4; j++) acc[i][j] = 0ull;

    float4 ra[4], rb;
#pragma unroll
    for (int c = 0; c < 4; c++)
        ra[c] = avalid ? *(const float4*)(Aptr + c * 4) : make_float4(0.f, 0.f, 0.f, 0.f);
    rb = *(const float4*)(Bptr);
#pragma unroll
    for (int c = 0; c < 4; c++) {
        As[0][c * 4 + 0][tid] = ra[c].x;
        As[0][c * 4 + 1][tid] = ra[c].y;
        As[0][c * 4 + 2][tid] = ra[c].z;
        As[0][c * 4 + 3][tid] = ra[c].w;
    }
    *(float4*)(&Bs[0][brow][bcol4 * 4]) = rb;
    __syncthreads();

    for (int t = 0; t < KTILES; t++) {
        int cur = t & 1, nxt = cur ^ 1;
        if (t + 1 < KTILES) {
            int k0 = (t + 1) * BK;
#pragma unroll
            for (int c = 0; c < 4; c++)
                ra[c] = avalid ? *(const float4*)(Aptr + k0 + c * 4) : make_float4(0.f, 0.f, 0.f, 0.f);
            rb = *(const float4*)(Bptr + (size_t)k0 * SD);
        }
#pragma unroll
        for (int k = 0; k < BK; k++) {
            ulonglong2 bb0 = *(const ulonglong2*)(&Bs[cur][k][tx * 8]);
            ulonglong2 bb1 = *(const ulonglong2*)(&Bs[cur][k][tx * 8 + 4]);
            unsigned long long b2[4] = {bb0.x, bb0.y, bb1.x, bb1.y};
            float4 a0 = *(const float4*)(&As[cur][k][ty * 8]);
            float4 a1 = *(const float4*)(&As[cur][k][ty * 8 + 4]);
            unsigned long long a2[8];
            a2[0] = bcast2(a0.x); a2[1] = bcast2(a0.y); a2[2] = bcast2(a0.z); a2[3] = bcast2(a0.w);
            a2[4] = bcast2(a1.x); a2[5] = bcast2(a1.y); a2[6] = bcast2(a1.z); a2[7] = bcast2(a1.w);
#pragma unroll
            for (int i = 0; i < 8; i++)
#pragma unroll
                for (int j = 0; j < 4; j++)
                    ffma2(acc[i][j], a2[i], b2[j]);
        }
        if (t + 1 < KTILES) {
#pragma unroll
            for (int c = 0; c < 4; c++) {
                As[nxt][c * 4 + 0][tid] = ra[c].x;
                As[nxt][c * 4 + 1][tid] = ra[c].y;
                As[nxt][c * 4 + 2][tid] = ra[c].z;
                As[nxt][c * 4 + 3][tid] = ra[c].w;
            }
            *(float4*)(&Bs[nxt][brow][bcol4 * 4]) = rb;
        }
        __syncthreads();
    }

    int gcol = bn + tx * 8;
#pragma unroll
    for (int i = 0; i < 8; i++) {
        int grow = bm + ty * 8 + i;
        if (grow >= M) continue;
        float2 u0 = unpack2(acc[i][0]);
        float2 u1 = unpack2(acc[i][1]);
        float2 u2 = unpack2(acc[i][2]);
        float2 u3 = unpack2(acc[i][3]);
        float* crow = C + (size_t)grow * SD + gcol;
        if (accumulate) {
            float4 c0 = *(float4*)crow;
            float4 c1 = *(float4*)(crow + 4);
            *(float4*)crow       = make_float4(c0.x + u0.x, c0.y + u0.y, c0.z + u1.x, c0.w + u1.y);
            *(float4*)(crow + 4) = make_float4(c1.x + u2.x, c1.y + u2.y, c1.z + u3.x, c1.w + u3.y);
        } else {
            *(float4*)crow       = make_float4(u0.x, u0.y, u1.x, u1.y);
            *(float4*)(crow + 4) = make_float4(u2.x, u2.y, u3.x, u3.y);
        }
    }
}

// Fused hinge loss: one block per pair t.
__global__ __launch_bounds__(256) void loss_kernel(const int* __restrict__ pl,
                                                   const int* __restrict__ pr,
                                                   const int* __restrict__ nr,
                                                   const int* __restrict__ nl,
                                                   const float* __restrict__ mask,
                                                   const float* __restrict__ node,
                                                   float* __restrict__ out) {
    __shared__ float4 sl[D4], sr[D4];
    __shared__ float wpart[8];
    __shared__ float s_dm;
    int t    = blockIdx.x;
    int tid  = threadIdx.x;
    int lane = tid & 31;
    int wid  = tid >> 5;

    const float4* xl = (const float4*)(node + (size_t)pl[t] * SD);
    const float4* xr = (const float4*)(node + (size_t)pr[t] * SD);
    float d = 0.f;
    if (tid < D4) {
        float4 a = xl[tid], b = xr[tid];
        sl[tid] = a; sr[tid] = b;
        d = fabsf(a.x - b.x) + fabsf(a.y - b.y) + fabsf(a.z - b.z) + fabsf(a.w - b.w);
    }
    d = warp_sum(d);
    if (lane == 0) wpart[wid] = d;
    __syncthreads();
    if (tid == 0) s_dm = wpart[0] + wpart[1] + wpart[2] + GAMMA_F;
    __syncthreads();
    float dm = s_dm;

    float hsum = 0.f;
    for (int k = wid; k < K_N; k += 8) {
        int i = t * K_N + k;
        const float4* xR = (const float4*)(node + (size_t)nr[i] * SD);
        const float4* xL = (const float4*)(node + (size_t)nl[i] * SD);
        float s1 = 0.f, s2 = 0.f;
#pragma unroll
        for (int it = 0; it < 3; it++) {
            int j = lane + it * 32;
            if (j < D4) {
                float4 a = sl[j], b = sr[j], cr = xR[j], cl = xL[j];
                s1 += fabsf(a.x - cr.x) + fabsf(a.y - cr.y) + fabsf(a.z - cr.z) + fabsf(a.w - cr.w);
                s2 += fabsf(cl.x - b.x) + fabsf(cl.y - b.y) + fabsf(cl.z - b.z) + fabsf(cl.w - b.w);
            }
        }
        s1 = warp_sum(s1);
        s2 = warp_sum(s2);
        if (lane == 0) hsum += (fmaxf(dm - s1, 0.f) + fmaxf(dm - s2, 0.f)) * mask[i];
    }
    if (lane == 0) wpart[wid] = hsum;
    __syncthreads();
    if (tid == 0) {
        float tot = 0.f;
#pragma unroll
        for (int w = 0; w < 8; w++) tot += wpart[w];
        atomicAdd(out, tot * 0.5f);
    }
}

// ---------------- host ----------------
extern "C" void kernel_launch(void* const* d_in, const int* in_sizes, int n_in,
                              void* d_out, int out_size) {
    const float* we    = (const float*)d_in[0];
    const float* kgw   = (const float*)d_in[1];
    const float* bg    = (const float*)d_in[2];
    const float* W1    = (const float*)d_in[3];
    const float* W2    = (const float*)d_in[4];
    const float* Dense = (const float*)d_in[5];
    const float* Bias  = (const float*)d_in[6];
    const int*   hr_rows = (const int*)d_in[7];
    const int*   hr_cols = (const int*)d_in[8];
    const float* hr_vals = (const float*)d_in[9];
    const int*   tr_rows = (const int*)d_in[10];
    const int*   tr_cols = (const int*)d_in[11];
    const float* tr_vals = (const float*)d_in[12];
    const int*   er_rows = (const int*)d_in[13];
    const int*   er_cols = (const int*)d_in[14];
    const float* er_vals = (const float*)d_in[15];
    const int*   adj_rows = (const int*)d_in[16];
    const int*   adj_cols = (const int*)d_in[17];
    const float* adj_vals = (const float*)d_in[18];
    const int*   pos_left  = (const int*)d_in[19];
    const int*   pos_right = (const int*)d_in[20];
    const int*   neg_right = (const int*)d_in[21];
    const int*   neg_left  = (const int*)d_in[22];
    const float* mask      = (const float*)d_in[23];
    float* out = (float*)d_out;

    int nnz_hr  = in_sizes[7];
    int nnz_tr  = in_sizes[10];
    int nnz_er  = in_sizes[13];
    int nnz_adj = in_sizes[16];

    float *p_emb, *p_A1, *p_A2, *p_A3, *p_A5, *p_A6, *p_Lm, *p_Rm, *p_P, *p_Wt;
    __nv_bfloat16 *p_Bh, *p_Bl, *p_Ch, *p_Cl, *p_WTh, *p_WTl;
    int *p_adj_ptr, *p_adj_cur, *p_adj_perm, *p_er_ptr, *p_er_cur, *p_er_perm, *p_bsum;
    cudaGetSymbolAddress((void**)&p_emb, g_emb);
    cudaGetSymbolAddress((void**)&p_A1,  g_A1);
    cudaGetSymbolAddress((void**)&p_A2,  g_A2);
    cudaGetSymbolAddress((void**)&p_A3,  g_A3);
    cudaGetSymbolAddress((void**)&p_A5,  g_A5);
    cudaGetSymbolAddress((void**)&p_A6,  g_A6);
    cudaGetSymbolAddress((void**)&p_Lm,  g_Lm);
    cudaGetSymbolAddress((void**)&p_Rm,  g_Rm);
    cudaGetSymbolAddress((void**)&p_P,   g_P);
    cudaGetSymbolAddress((void**)&p_Wt,  g_Wt);
    cudaGetSymbolAddress((void**)&p_Bh,  g_Bh);
    cudaGetSymbolAddress((void**)&p_Bl,  g_Bl);
    cudaGetSymbolAddress((void**)&p_Ch,  g_Ch);
    cudaGetSymbolAddress((void**)&p_Cl,  g_Cl);
    cudaGetSymbolAddress((void**)&p_WTh, g_WTh);
    cudaGetSymbolAddress((void**)&p_WTl, g_WTl);
    cudaGetSymbolAddress((void**)&p_adj_ptr,  g_adj_ptr);
    cudaGetSymbolAddress((void**)&p_adj_cur,  g_adj_cur);
    cudaGetSymbolAddress((void**)&p_adj_perm, g_adj_perm);
    cudaGetSymbolAddress((void**)&p_er_ptr,   g_er_ptr);
    cudaGetSymbolAddress((void**)&p_er_cur,   g_er_cur);
    cudaGetSymbolAddress((void**)&p_er_perm,  g_er_perm);
    cudaGetSymbolAddress((void**)&p_bsum,     g_bsum);

    cudaFuncSetAttribute(mgemm_kernel, cudaFuncAttributeMaxDynamicSharedMemorySize, MM_SMEM);

    dim3 mmGrid(SD / MMN, (E_N + 127) / 128);       // (2, 782)
    dim3 gemmGridR(SD / BN, (R_N + BM - 1) / BM);
    const int NB_E = (E_N + 1023) / 1024;           // 98

    // 1-3, then launch #4 = first HMMA GEMM (profiled)
    wsplit_kernel<<<(4 * WOFF + 255) / 256, 256>>>(Dense, W1, W2, kgw);
    normalize_kernel<<<(E_N * 32) / 256, 256>>>(we);
    zero4_kernel<<<(R_N * SD / 4 + 255) / 256, 256>>>((float4*)p_Lm, R_N * SD / 4);
    mgemm_kernel<<<mmGrid, 256, MM_SMEM>>>(p_Bh, p_Bl, p_WTh, p_WTl, p_A1, E_N, 0, 0, 0, 0, 0, 0);

    // ---- CSR build: adj (uses g_adj_cur as count buffer first) ----
    zcnt_kernel<<<(E_N + 255) / 256, 256>>>(p_adj_cur, E_N);
    hist_kernel<<<(nnz_adj + 255) / 256, 256>>>(adj_rows, nnz_adj, p_adj_cur);
    scan1_kernel<<<NB_E, 256>>>(p_adj_cur, E_N, p_bsum);
    scan2_kernel<<<1, 32>>>(p_bsum, NB_E);
    scan3_kernel<<<NB_E, 256>>>(p_adj_cur, p_bsum, E_N, p_adj_ptr, p_adj_cur);
    scatter_kernel<<<(nnz_adj + 255) / 256, 256>>>(adj_rows, nnz_adj, p_adj_cur, p_adj_perm);

    // ---- CSR build: er ----
    zcnt_kernel<<<(E_N + 255) / 256, 256>>>(p_er_cur, E_N);
    hist_kernel<<<(nnz_er + 255) / 256, 256>>>(er_rows, nnz_er, p_er_cur);
    scan1_kernel<<<NB_E, 256>>>(p_er_cur, E_N, p_bsum);
    scan2_kernel<<<1, 32>>>(p_bsum, NB_E);
    scan3_kernel<<<NB_E, 256>>>(p_er_cur, p_bsum, E_N, p_er_ptr, p_er_cur);
    scatter_kernel<<<(nnz_er + 255) / 256, 256>>>(er_rows, nnz_er, p_er_cur, p_er_perm);

    // relation aggregation (scatter; small outputs)
    zero4_kernel<<<(R_N * SD / 4 + 255) / 256, 256>>>((float4*)p_Rm, R_N * SD / 4);
    spmm_kernel<<<(nnz_hr + 7) / 8, 256>>>(hr_rows, hr_cols, hr_vals, nnz_hr, p_emb, p_Lm);
    spmm_kernel<<<(nnz_tr + 7) / 8, 256>>>(tr_rows, tr_cols, tr_vals, nnz_tr, p_emb, p_Rm);

    // P = L @ Db1 + Rm @ Db2
    pad_weights_kernel<<<(2 * SD * SD + 255) / 256, 256>>>(Dense);
    sgemm_kernel<<<gemmGridR, 256>>>(p_Lm, p_Wt, p_P, R_N, 0);
    sgemm_kernel<<<gemmGridR, 256>>>(p_Rm, p_Wt + SD * SD, p_P, R_N, 1);

    zero_out_kernel<<<1, 1>>>(out);

    // h = emb + relu(A1 + er_gather + Bias)  -> A2, splits -> Ch/Cl  (fused)
    h_er_kernel<<<(E_N * 32 + 255) / 256, 256>>>(p_er_ptr, p_er_perm, er_cols, er_vals, Bias);

    // layer 1: t1 = h@W1 -> A3; gcn1 gather -> A5; gate GEMM fuses highway -> A6 (+ splits -> Bh/Bl)
    mgemm_kernel<<<mmGrid, 256, MM_SMEM>>>(p_Ch, p_Cl, p_WTh + 1 * WOFF, p_WTl + 1 * WOFF, p_A3, E_N, 0, 0, 0, 0, 0, 0);
    gspmm_kernel<<<(E_N * 32 + 255) / 256, 256>>>(p_adj_ptr, p_adj_perm, adj_cols, adj_vals, p_A3, p_A5, E_N);
    mgemm_kernel<<<mmGrid, 256, MM_SMEM>>>(p_Ch, p_Cl, p_WTh + 3 * WOFF, p_WTl + 3 * WOFF, p_A6, E_N, 4, p_A2, p_A5, bg, p_Bh, p_Bl);

    // layer 2: t2 = hg1@W2 -> A3; gcn2 gather -> A1; gate GEMM fuses highway -> node (A2)
    mgemm_kernel<<<mmGrid, 256, MM_SMEM>>>(p_Bh, p_Bl, p_WTh + 2 * WOFF, p_WTl + 2 * WOFF, p_A3, E_N, 0, 0, 0, 0, 0, 0);
    gspmm_kernel<<<(E_N * 32 + 255) / 256, 256>>>(p_adj_ptr, p_adj_perm, adj_cols, adj_vals, p_A3, p_A1, E_N);
    mgemm_kernel<<<mmGrid, 256, MM_SMEM>>>(p_Bh, p_Bl, p_WTh + 3 * WOFF, p_WTl + 3 * WOFF, p_A2, E_N, 3, p_A6, p_A1, bg, 0, 0);

    // fused loss
    loss_kernel<<<T_N, 256>>>(pos_left, pos_right, neg_right, neg_left, mask, p_A2, out);
    (void)n_in; (void)out_size;
}